// round 3
// baseline (speedup 1.0000x reference)
#include <cuda_runtime.h>
#include <math.h>
#include <stdint.h>

// GPT-2 stack: L=8, E=1024, H=16, T=2048, B=1, DH=64, fp32 in/out.
#define TT 2048
#define EE 1024
#define NH 16
#define HD 64
#define NL 8

// ---------------- scratch (device globals; no allocation allowed) ----------
__device__ float g_h  [TT * EE];        // residual stream
__device__ float g_y  [TT * EE];        // LN output (tf32-rounded)
__device__ float g_qkv[TT * 3 * EE];    // QKV (fp32, consumed by attention)
__device__ float g_att[TT * EE];        // attention output (tf32-rounded)
__device__ float g_m1 [TT * 4 * EE];    // MLP hidden (tf32-rounded)

// tf32-rounded weight copies (rounded once per launch)
__device__ float g_wqkv[NL * EE * 3 * EE];
__device__ float g_wproj[NL * EE * EE];
__device__ float g_wfc [NL * EE * 4 * EE];
__device__ float g_wfc2[NL * 4 * EE * EE];

__device__ __forceinline__ uint32_t f2tf32(float x) {
    uint32_t r;
    asm("cvt.rna.tf32.f32 %0, %1;" : "=r"(r) : "f"(x));
    return r;
}
__device__ __forceinline__ float roundtf32(float x) {
    return __uint_as_float(f2tf32(x));
}

// ---------------- weight rounding pass --------------------------------------
__global__ __launch_bounds__(256) void round_kernel(
    const float* __restrict__ src, float* __restrict__ dst, int n4)
{
    int i = blockIdx.x * 256 + threadIdx.x;
    int stride = gridDim.x * 256;
    for (; i < n4; i += stride) {
        float4 v = reinterpret_cast<const float4*>(src)[i];
        v.x = roundtf32(v.x); v.y = roundtf32(v.y);
        v.z = roundtf32(v.z); v.w = roundtf32(v.w);
        reinterpret_cast<float4*>(dst)[i] = v;
    }
}

// ---------------- LayerNorm: one block per token row ------------------------
__global__ __launch_bounds__(256) void ln_kernel(
    const float* __restrict__ h, const float* __restrict__ w,
    const float* __restrict__ b, float* __restrict__ y)
{
    const int row = blockIdx.x;
    const int tid = threadIdx.x;            // 256 threads, 4 floats each
    const float4* hr = reinterpret_cast<const float4*>(h + (size_t)row * EE);
    float4 v = hr[tid];
    float s  = v.x + v.y + v.z + v.w;
    float sq = v.x*v.x + v.y*v.y + v.z*v.z + v.w*v.w;

    __shared__ float ss[8], ssq[8];
    #pragma unroll
    for (int off = 16; off > 0; off >>= 1) {
        s  += __shfl_xor_sync(0xffffffffu, s,  off);
        sq += __shfl_xor_sync(0xffffffffu, sq, off);
    }
    int lane = tid & 31, wid = tid >> 5;
    if (lane == 0) { ss[wid] = s; ssq[wid] = sq; }
    __syncthreads();
    if (tid == 0) {
        float S = 0.f, Q = 0.f;
        #pragma unroll
        for (int i = 0; i < 8; i++) { S += ss[i]; Q += ssq[i]; }
        ss[0] = S; ssq[0] = Q;
    }
    __syncthreads();
    const float mu  = ss[0] * (1.0f / EE);
    const float var = ssq[0] * (1.0f / EE) - mu * mu;
    const float inv = rsqrtf(var + 1e-5f);

    float4 wv = reinterpret_cast<const float4*>(w)[tid];
    float4 bv = reinterpret_cast<const float4*>(b)[tid];
    float4 o;
    o.x = roundtf32((v.x - mu) * inv * wv.x + bv.x);
    o.y = roundtf32((v.y - mu) * inv * wv.y + bv.y);
    o.z = roundtf32((v.z - mu) * inv * wv.z + bv.z);
    o.w = roundtf32((v.w - mu) * inv * wv.w + bv.w);
    reinterpret_cast<float4*>(y + (size_t)row * EE)[tid] = o;
}

// ---------------- TF32 tensor-core GEMM -------------------------------------
// Inputs A, B MUST already be tf32-rounded (low 13 mantissa bits zero).
// MODE 0: bias only; MODE 1: gelu(x+bias), tf32-rounded out; MODE 2: C += x+bias.
// BN=128: 8 warps as 4m x 2n, warp tile 32x64.  BN=64: warp tile 32x32.

__device__ __forceinline__ float gelu_tanh(float x) {
    const float c0 = 0.7978845608028654f;   // sqrt(2/pi)
    float t = tanhf(c0 * (x + 0.044715f * x * x * x));
    return 0.5f * x * (1.0f + t);
}

__device__ __forceinline__ void mma_tf32(float c[4], const uint32_t a[4], const uint32_t b[2]) {
    asm volatile(
        "mma.sync.aligned.m16n8k8.row.col.f32.tf32.tf32.f32 "
        "{%0,%1,%2,%3}, {%4,%5,%6,%7}, {%8,%9}, {%0,%1,%2,%3};\n"
        : "+f"(c[0]), "+f"(c[1]), "+f"(c[2]), "+f"(c[3])
        : "r"(a[0]), "r"(a[1]), "r"(a[2]), "r"(a[3]),
          "r"(b[0]), "r"(b[1]));
}

#define CP16(dst, src) asm volatile("cp.async.cg.shared.global [%0], [%1], 16;\n" :: "r"(dst), "l"(src))
#define CP_COMMIT()    asm volatile("cp.async.commit_group;\n")
#define CP_WAIT(n)     asm volatile("cp.async.wait_group %0;\n" :: "n"(n))

#define AST 36                         // (36m+k)%32 = (4m+k)%32 -> conflict-free
#define A_SZ (128 * AST)

template <int MODE, int BN>
__global__ __launch_bounds__(256, 2) void mma_gemm(
    const float* __restrict__ A, const float* __restrict__ B,
    const float* __restrict__ bias, float* __restrict__ C,
    int M, int N, int K)
{
    constexpr int BST = BN + 8;        // (BST*k)%32 = 8k -> conflict-free
    constexpr int B_SZ = 32 * BST;
    constexpr int NT   = BN / 16;      // n subtiles of 8 per warp

    extern __shared__ float sm[];
    float* Abuf[2] = { sm,        sm + A_SZ + B_SZ };
    float* Bbuf[2] = { sm + A_SZ, sm + 2*A_SZ + B_SZ };

    const int tid  = threadIdx.x;
    const int lane = tid & 31;
    const int warp = tid >> 5;
    const int wm   = (warp & 3) * 32;       // 4 warps over 128 m
    const int wn   = (warp >> 2) * (BN/2);  // 2 warps over BN
    const int g    = lane >> 2;             // 0..7
    const int tk   = lane & 3;              // 0..3

    const int bm = blockIdx.y * 128;
    const int bn = blockIdx.x * BN;

    uint32_t a_s[2], b_s[2];
    a_s[0] = (uint32_t)__cvta_generic_to_shared(Abuf[0]);
    a_s[1] = (uint32_t)__cvta_generic_to_shared(Abuf[1]);
    b_s[0] = (uint32_t)__cvta_generic_to_shared(Bbuf[0]);
    b_s[1] = (uint32_t)__cvta_generic_to_shared(Bbuf[1]);

    float acc[2][NT][4];
    #pragma unroll
    for (int mt = 0; mt < 2; mt++)
        #pragma unroll
        for (int nt = 0; nt < NT; nt++)
            #pragma unroll
            for (int i = 0; i < 4; i++) acc[mt][nt][i] = 0.f;

    auto load_tile = [&](int buf, int k0) {
        #pragma unroll
        for (int i = 0; i < 4; i++) {
            int idx = tid + 256 * i;
            int r = idx >> 3, c = (idx & 7) * 4;        // 128 rows x 8 chunks
            CP16(a_s[buf] + (uint32_t)(r * AST + c) * 4,
                 A + (size_t)(bm + r) * K + k0 + c);
        }
        constexpr int CPR = BN / 4;                      // chunks per B row
        #pragma unroll
        for (int i = 0; i < BN / 32; i++) {
            int idx = tid + 256 * i;
            int r = idx / CPR, c = (idx % CPR) * 4;      // 32 rows x CPR chunks
            CP16(b_s[buf] + (uint32_t)(r * BST + c) * 4,
                 B + (size_t)(k0 + r) * N + bn + c);
        }
        CP_COMMIT();
    };

    const int nk = K / 32;
    load_tile(0, 0);

    for (int t = 0; t < nk; t++) {
        const int buf = t & 1;
        if (t + 1 < nk) {
            load_tile(buf ^ 1, (t + 1) * 32);
            CP_WAIT(1);
        } else {
            CP_WAIT(0);
        }
        __syncthreads();

        const float* Ab = Abuf[buf];
        const float* Bb = Bbuf[buf];

        #pragma unroll
        for (int kk = 0; kk < 4; kk++) {
            uint32_t af[2][4], bf[NT][2];
            const int kc = kk * 8;
            #pragma unroll
            for (int mt = 0; mt < 2; mt++) {
                int r0 = wm + mt * 16;
                af[mt][0] = __float_as_uint(Ab[(r0 + g    ) * AST + kc + tk    ]);
                af[mt][1] = __float_as_uint(Ab[(r0 + g + 8) * AST + kc + tk    ]);
                af[mt][2] = __float_as_uint(Ab[(r0 + g    ) * AST + kc + tk + 4]);
                af[mt][3] = __float_as_uint(Ab[(r0 + g + 8) * AST + kc + tk + 4]);
            }
            #pragma unroll
            for (int nt = 0; nt < NT; nt++) {
                int c0 = wn + nt * 8 + g;
                bf[nt][0] = __float_as_uint(Bb[(kc + tk    ) * BST + c0]);
                bf[nt][1] = __float_as_uint(Bb[(kc + tk + 4) * BST + c0]);
            }
            #pragma unroll
            for (int mt = 0; mt < 2; mt++)
                #pragma unroll
                for (int nt = 0; nt < NT; nt++)
                    mma_tf32(acc[mt][nt], af[mt], bf[nt]);
        }
        __syncthreads();
    }

    #pragma unroll
    for (int mt = 0; mt < 2; mt++) {
        const int row0 = bm + wm + mt * 16 + g;
        #pragma unroll
        for (int nt = 0; nt < NT; nt++) {
            const int col = bn + wn + nt * 8 + 2 * tk;
            float2 bv = *reinterpret_cast<const float2*>(bias + col);
            float o0 = acc[mt][nt][0] + bv.x;
            float o1 = acc[mt][nt][1] + bv.y;
            float o2 = acc[mt][nt][2] + bv.x;
            float o3 = acc[mt][nt][3] + bv.y;
            if (MODE == 1) {
                o0 = roundtf32(gelu_tanh(o0)); o1 = roundtf32(gelu_tanh(o1));
                o2 = roundtf32(gelu_tanh(o2)); o3 = roundtf32(gelu_tanh(o3));
            }
            float* p0 = C + (size_t)row0 * N + col;
            float* p1 = C + (size_t)(row0 + 8) * N + col;
            if (MODE == 2) {
                float2 c0 = *reinterpret_cast<const float2*>(p0);
                float2 c1 = *reinterpret_cast<const float2*>(p1);
                o0 += c0.x; o1 += c0.y; o2 += c1.x; o3 += c1.y;
            }
            *reinterpret_cast<float2*>(p0) = make_float2(o0, o1);
            *reinterpret_cast<float2*>(p1) = make_float2(o2, o3);
        }
    }
}

// ---------------- Flash-style causal attention ------------------------------
__global__ __launch_bounds__(256) void flash_attn_kernel(
    const float* __restrict__ qkv, float* __restrict__ att)
{
    __shared__ float Qs[64][65];
    __shared__ float Ks[32][65];
    __shared__ float Vs[32][65];
    __shared__ float Ps[64][33];

    const int qb = blockIdx.x;
    const int h  = blockIdx.y;
    const int tid = threadIdx.x;
    const int ty = tid >> 4, tx = tid & 15;
    const int q0 = qb * 64;
    const int ld = 3 * EE;
    const int qoff = h * HD;

    for (int idx = tid; idx < 64 * 64; idx += 256) {
        int r = idx >> 6, d = idx & 63;
        Qs[r][d] = qkv[(size_t)(q0 + r) * ld + qoff + d];
    }

    float O[4][4], m[4], l[4];
    #pragma unroll
    for (int i = 0; i < 4; i++) {
        m[i] = -1e30f; l[i] = 0.f;
        #pragma unroll
        for (int j = 0; j < 4; j++) O[i][j] = 0.f;
    }

    const int kbmax = (q0 + 63) >> 5;   // inclusive (causal)
    for (int kb = 0; kb <= kbmax; kb++) {
        const int k0 = kb * 32;
        for (int idx = tid; idx < 32 * 64; idx += 256) {
            int r = idx >> 6, d = idx & 63;
            Ks[r][d] = qkv[(size_t)(k0 + r) * ld +     EE + qoff + d];
            Vs[r][d] = qkv[(size_t)(k0 + r) * ld + 2 * EE + qoff + d];
        }
        __syncthreads();

        float S[4][2];
        #pragma unroll
        for (int i = 0; i < 4; i++)
            #pragma unroll
            for (int j = 0; j < 2; j++) S[i][j] = 0.f;

        #pragma unroll 8
        for (int d = 0; d < 64; d++) {
            float qv[4], kv[2];
            #pragma unroll
            for (int i = 0; i < 4; i++) qv[i] = Qs[ty*4+i][d];
            #pragma unroll
            for (int j = 0; j < 2; j++) kv[j] = Ks[tx*2+j][d];
            #pragma unroll
            for (int i = 0; i < 4; i++)
                #pragma unroll
                for (int j = 0; j < 2; j++)
                    S[i][j] = fmaf(qv[i], kv[j], S[i][j]);
        }

        #pragma unroll
        for (int i = 0; i < 4; i++) {
            int gq = q0 + ty*4 + i;
            #pragma unroll
            for (int j = 0; j < 2; j++) {
                int gk = k0 + tx*2 + j;
                S[i][j] = (gk <= gq) ? S[i][j] * 0.125f : -10000.0f;
            }
        }

        #pragma unroll
        for (int i = 0; i < 4; i++) {
            float rm = fmaxf(S[i][0], S[i][1]);
            #pragma unroll
            for (int off = 8; off > 0; off >>= 1)
                rm = fmaxf(rm, __shfl_xor_sync(0xffffffffu, rm, off));
            float mn = fmaxf(m[i], rm);
            float p0 = __expf(S[i][0] - mn);
            float p1 = __expf(S[i][1] - mn);
            float rs = p0 + p1;
            #pragma unroll
            for (int off = 8; off > 0; off >>= 1)
                rs += __shfl_xor_sync(0xffffffffu, rs, off);
            float corr = __expf(m[i] - mn);
            l[i] = l[i] * corr + rs;
            m[i] = mn;
            #pragma unroll
            for (int j = 0; j < 4; j++) O[i][j] *= corr;
            Ps[ty*4+i][tx*2+0] = p0;
            Ps[ty*4+i][tx*2+1] = p1;
        }
        __syncthreads();

        #pragma unroll 8
        for (int k = 0; k < 32; k++) {
            float pv[4], vv[4];
            #pragma unroll
            for (int i = 0; i < 4; i++) pv[i] = Ps[ty*4+i][k];
            #pragma unroll
            for (int j = 0; j < 4; j++) vv[j] = Vs[k][tx*4+j];
            #pragma unroll
            for (int i = 0; i < 4; i++)
                #pragma unroll
                for (int j = 0; j < 4; j++)
                    O[i][j] = fmaf(pv[i], vv[j], O[i][j]);
        }
        __syncthreads();
    }

    #pragma unroll
    for (int i = 0; i < 4; i++) {
        float invl = 1.0f / l[i];
        int gq = q0 + ty*4 + i;
        #pragma unroll
        for (int j = 0; j < 4; j++)
            att[(size_t)gq * EE + qoff + tx*4 + j] = roundtf32(O[i][j] * invl);
    }
}

// ---------------- host orchestration ---------------------------------------
extern "C" void kernel_launch(void* const* d_in, const int* in_sizes, int n_in,
                              void* d_out, int out_size)
{
    const float* x      = (const float*)d_in[0];
    const float* ln1_w  = (const float*)d_in[1];
    const float* ln1_b  = (const float*)d_in[2];
    const float* attn_w = (const float*)d_in[3];
    const float* attn_b = (const float*)d_in[4];
    const float* proj_w = (const float*)d_in[5];
    const float* proj_b = (const float*)d_in[6];
    const float* ln2_w  = (const float*)d_in[7];
    const float* ln2_b  = (const float*)d_in[8];
    const float* fc_w   = (const float*)d_in[9];
    const float* fc_b   = (const float*)d_in[10];
    const float* fc2_w  = (const float*)d_in[11];
    const float* fc2_b  = (const float*)d_in[12];

    float *h, *y, *qkv, *att, *m1, *wqkv, *wproj, *wfc, *wfc2;
    cudaGetSymbolAddress((void**)&h,    g_h);
    cudaGetSymbolAddress((void**)&y,    g_y);
    cudaGetSymbolAddress((void**)&qkv,  g_qkv);
    cudaGetSymbolAddress((void**)&att,  g_att);
    cudaGetSymbolAddress((void**)&m1,   g_m1);
    cudaGetSymbolAddress((void**)&wqkv, g_wqkv);
    cudaGetSymbolAddress((void**)&wproj,g_wproj);
    cudaGetSymbolAddress((void**)&wfc,  g_wfc);
    cudaGetSymbolAddress((void**)&wfc2, g_wfc2);

    constexpr int SMEM_128 = (A_SZ + 32 * (128 + 8)) * 2 * 4;
    constexpr int SMEM_64  = (A_SZ + 32 * ( 64 + 8)) * 2 * 4;
    cudaFuncSetAttribute(mma_gemm<0,128>, cudaFuncAttributeMaxDynamicSharedMemorySize, SMEM_128);
    cudaFuncSetAttribute(mma_gemm<1,128>, cudaFuncAttributeMaxDynamicSharedMemorySize, SMEM_128);
    cudaFuncSetAttribute(mma_gemm<2,64>,  cudaFuncAttributeMaxDynamicSharedMemorySize, SMEM_64);

    // round all weights to tf32 once (per replay)
    round_kernel<<<592, 256>>>(attn_w, wqkv,  NL * EE * 3 * EE / 4);
    round_kernel<<<592, 256>>>(proj_w, wproj, NL * EE * EE / 4);
    round_kernel<<<592, 256>>>(fc_w,   wfc,   NL * EE * 4 * EE / 4);
    round_kernel<<<592, 256>>>(fc2_w,  wfc2,  NL * 4 * EE * EE / 4);

    cudaMemcpyAsync(h, x, (size_t)TT * EE * sizeof(float),
                    cudaMemcpyDeviceToDevice, 0);

    const dim3 blk(256);
    const dim3 gLN(TT);
    const dim3 gQKV(3 * EE / 128, TT / 128);   // (24,16)
    const dim3 gPROJ(EE / 64, TT / 128);       // (16,16) = 256 CTAs
    const dim3 gFC(4 * EE / 128, TT / 128);    // (32,16)
    const dim3 gFC2(EE / 64, TT / 128);        // (16,16) = 256 CTAs
    const dim3 gATT(TT / 64, NH);              // (32,16)

    for (int lyr = 0; lyr < NL; lyr++) {
        const float* aw  = wqkv  + (size_t)lyr * EE * 3 * EE;
        const float* ab  = attn_b + (size_t)lyr * 3 * EE;
        const float* pw  = wproj + (size_t)lyr * EE * EE;
        const float* pb  = proj_b + (size_t)lyr * EE;
        const float* fw  = wfc   + (size_t)lyr * EE * 4 * EE;
        const float* fb  = fc_b   + (size_t)lyr * 4 * EE;
        const float* f2w = wfc2  + (size_t)lyr * 4 * EE * EE;
        const float* f2b = fc2_b  + (size_t)lyr * EE;

        // attn block
        ln_kernel<<<gLN, blk>>>(h, ln1_w + (size_t)lyr * EE, ln1_b + (size_t)lyr * EE, y);
        mma_gemm<0,128><<<gQKV, blk, SMEM_128>>>(y, aw, ab, qkv, TT, 3 * EE, EE);
        flash_attn_kernel<<<gATT, blk>>>(qkv, att);
        mma_gemm<2,64><<<gPROJ, blk, SMEM_64>>>(att, pw, pb, h, TT, EE, EE);

        // MLP block
        ln_kernel<<<gLN, blk>>>(h, ln2_w + (size_t)lyr * EE, ln2_b + (size_t)lyr * EE, y);
        mma_gemm<1,128><<<gFC, blk, SMEM_128>>>(y, fw, fb, m1, TT, 4 * EE, EE);
        mma_gemm<2,64><<<gFC2, blk, SMEM_64>>>(m1, f2w, f2b, h, TT, EE, 4 * EE);
    }

    cudaMemcpyAsync(d_out, h, (size_t)TT * EE * sizeof(float),
                    cudaMemcpyDeviceToDevice, 0);
}

// round 5
// speedup vs baseline: 1.4305x; 1.4305x over previous
#include <cuda_runtime.h>
#include <math.h>
#include <stdint.h>

// GPT-2 stack: L=8, E=1024, H=16, T=2048, B=1, DH=64, fp32 in/out.
#define TT 2048
#define EE 1024
#define NH 16
#define HD 64
#define NL 8

// ---------------- scratch (device globals; no allocation allowed) ----------
__device__ float g_h  [TT * EE];        // residual stream
__device__ float g_y  [TT * EE];        // LN output
__device__ float g_qkv[TT * 3 * EE];    // QKV
__device__ float g_att[TT * EE];        // attention output (merged heads)
__device__ float g_m1 [TT * 4 * EE];    // MLP hidden

// ---------------- helpers ----------------------------------------------------
__device__ __forceinline__ uint32_t f2tf32(float x) {
    uint32_t r;
    asm("cvt.rna.tf32.f32 %0, %1;" : "=r"(r) : "f"(x));
    return r;
}
__device__ __forceinline__ uint32_t smem_u32(const void* p) {
    return (uint32_t)__cvta_generic_to_shared(p);
}
__device__ __forceinline__ void mma_tf32(float c[4], const uint32_t a[4], const uint32_t b[2]) {
    asm volatile(
        "mma.sync.aligned.m16n8k8.row.col.f32.tf32.tf32.f32 "
        "{%0,%1,%2,%3}, {%4,%5,%6,%7}, {%8,%9}, {%0,%1,%2,%3};\n"
        : "+f"(c[0]), "+f"(c[1]), "+f"(c[2]), "+f"(c[3])
        : "r"(a[0]), "r"(a[1]), "r"(a[2]), "r"(a[3]),
          "r"(b[0]), "r"(b[1]));
}
#define CP16(dst, src) asm volatile("cp.async.cg.shared.global [%0], [%1], 16;\n" :: "r"(dst), "l"(src))
#define CP_COMMIT()    asm volatile("cp.async.commit_group;\n")
#define CP_WAIT(n)     asm volatile("cp.async.wait_group %0;\n" :: "n"(n))

__device__ __forceinline__ float gelu_tanh(float x) {
    const float c0 = 0.7978845608028654f;   // sqrt(2/pi)
    float t = tanhf(c0 * (x + 0.044715f * x * x * x));
    return 0.5f * x * (1.0f + t);
}

// ---------------- LayerNorm: one block per token row ------------------------
__global__ __launch_bounds__(256) void ln_kernel(
    const float* __restrict__ h, const float* __restrict__ w,
    const float* __restrict__ b, float* __restrict__ y)
{
    const int row = blockIdx.x;
    const int tid = threadIdx.x;
    const float4* hr = reinterpret_cast<const float4*>(h + (size_t)row * EE);
    float4 v = hr[tid];
    float s  = v.x + v.y + v.z + v.w;
    float sq = v.x*v.x + v.y*v.y + v.z*v.z + v.w*v.w;

    __shared__ float ss[8], ssq[8];
    #pragma unroll
    for (int off = 16; off > 0; off >>= 1) {
        s  += __shfl_xor_sync(0xffffffffu, s,  off);
        sq += __shfl_xor_sync(0xffffffffu, sq, off);
    }
    int lane = tid & 31, wid = tid >> 5;
    if (lane == 0) { ss[wid] = s; ssq[wid] = sq; }
    __syncthreads();
    if (tid == 0) {
        float S = 0.f, Q = 0.f;
        #pragma unroll
        for (int i = 0; i < 8; i++) { S += ss[i]; Q += ssq[i]; }
        ss[0] = S; ssq[0] = Q;
    }
    __syncthreads();
    const float mu  = ss[0] * (1.0f / EE);
    const float var = ssq[0] * (1.0f / EE) - mu * mu;
    const float inv = rsqrtf(var + 1e-5f);

    float4 wv = reinterpret_cast<const float4*>(w)[tid];
    float4 bv = reinterpret_cast<const float4*>(b)[tid];
    float4 o;
    o.x = (v.x - mu) * inv * wv.x + bv.x;
    o.y = (v.y - mu) * inv * wv.y + bv.y;
    o.z = (v.z - mu) * inv * wv.z + bv.z;
    o.w = (v.w - mu) * inv * wv.w + bv.w;
    reinterpret_cast<float4*>(y + (size_t)row * EE)[tid] = o;
}

// ---------------- TF32 tensor-core GEMM (mma.sync) ---------------------------
// MODE 0: bias; 1: gelu(x+bias); 2: C += x + bias.
#define AST 36                         // (36m+k)%32 = (4m+k)%32 -> conflict-free
#define A_SZ (128 * AST)

template <int MODE, int BN>
__global__ __launch_bounds__(256, 2) void mma_gemm(
    const float* __restrict__ A, const float* __restrict__ B,
    const float* __restrict__ bias, float* __restrict__ C,
    int M, int N, int K)
{
    constexpr int BST = BN + 8;        // (BST*k)%32 = 8k -> conflict-free
    constexpr int B_SZ = 32 * BST;
    constexpr int NT   = BN / 16;      // n subtiles of 8 per warp

    extern __shared__ float sm[];
    float* Abuf[2] = { sm,        sm + A_SZ + B_SZ };
    float* Bbuf[2] = { sm + A_SZ, sm + 2*A_SZ + B_SZ };

    const int tid  = threadIdx.x;
    const int lane = tid & 31;
    const int warp = tid >> 5;
    const int wm   = (warp & 3) * 32;
    const int wn   = (warp >> 2) * (BN/2);
    const int g    = lane >> 2;
    const int tk   = lane & 3;

    const int bm = blockIdx.y * 128;
    const int bn = blockIdx.x * BN;

    uint32_t a_s[2], b_s[2];
    a_s[0] = smem_u32(Abuf[0]); a_s[1] = smem_u32(Abuf[1]);
    b_s[0] = smem_u32(Bbuf[0]); b_s[1] = smem_u32(Bbuf[1]);

    float acc[2][NT][4];
    #pragma unroll
    for (int mt = 0; mt < 2; mt++)
        #pragma unroll
        for (int nt = 0; nt < NT; nt++)
            #pragma unroll
            for (int i = 0; i < 4; i++) acc[mt][nt][i] = 0.f;

    auto load_tile = [&](int buf, int k0) {
        #pragma unroll
        for (int i = 0; i < 4; i++) {
            int idx = tid + 256 * i;
            int r = idx >> 3, c = (idx & 7) * 4;
            CP16(a_s[buf] + (uint32_t)(r * AST + c) * 4,
                 A + (size_t)(bm + r) * K + k0 + c);
        }
        constexpr int CPR = BN / 4;
        #pragma unroll
        for (int i = 0; i < BN / 32; i++) {
            int idx = tid + 256 * i;
            int r = idx / CPR, c = (idx % CPR) * 4;
            CP16(b_s[buf] + (uint32_t)(r * BST + c) * 4,
                 B + (size_t)(k0 + r) * N + bn + c);
        }
        CP_COMMIT();
    };

    const int nk = K / 32;
    load_tile(0, 0);

    for (int t = 0; t < nk; t++) {
        const int buf = t & 1;
        if (t + 1 < nk) {
            load_tile(buf ^ 1, (t + 1) * 32);
            CP_WAIT(1);
        } else {
            CP_WAIT(0);
        }
        __syncthreads();

        const float* Ab = Abuf[buf];
        const float* Bb = Bbuf[buf];

        #pragma unroll
        for (int kk = 0; kk < 4; kk++) {
            uint32_t af[2][4], bf[NT][2];
            const int kc = kk * 8;
            #pragma unroll
            for (int mt = 0; mt < 2; mt++) {
                int r0 = wm + mt * 16;
                af[mt][0] = f2tf32(Ab[(r0 + g    ) * AST + kc + tk    ]);
                af[mt][1] = f2tf32(Ab[(r0 + g + 8) * AST + kc + tk    ]);
                af[mt][2] = f2tf32(Ab[(r0 + g    ) * AST + kc + tk + 4]);
                af[mt][3] = f2tf32(Ab[(r0 + g + 8) * AST + kc + tk + 4]);
            }
            #pragma unroll
            for (int nt = 0; nt < NT; nt++) {
                int c0 = wn + nt * 8 + g;
                bf[nt][0] = f2tf32(Bb[(kc + tk    ) * BST + c0]);
                bf[nt][1] = f2tf32(Bb[(kc + tk + 4) * BST + c0]);
            }
            #pragma unroll
            for (int mt = 0; mt < 2; mt++)
                #pragma unroll
                for (int nt = 0; nt < NT; nt++)
                    mma_tf32(acc[mt][nt], af[mt], bf[nt]);
        }
        __syncthreads();
    }

    #pragma unroll
    for (int mt = 0; mt < 2; mt++) {
        const int row0 = bm + wm + mt * 16 + g;
        #pragma unroll
        for (int nt = 0; nt < NT; nt++) {
            const int col = bn + wn + nt * 8 + 2 * tk;
            float2 bv = *reinterpret_cast<const float2*>(bias + col);
            float o0 = acc[mt][nt][0] + bv.x;
            float o1 = acc[mt][nt][1] + bv.y;
            float o2 = acc[mt][nt][2] + bv.x;
            float o3 = acc[mt][nt][3] + bv.y;
            if (MODE == 1) {
                o0 = gelu_tanh(o0); o1 = gelu_tanh(o1);
                o2 = gelu_tanh(o2); o3 = gelu_tanh(o3);
            }
            float* p0 = C + (size_t)row0 * N + col;
            float* p1 = C + (size_t)(row0 + 8) * N + col;
            if (MODE == 2) {
                float2 c0 = *reinterpret_cast<const float2*>(p0);
                float2 c1 = *reinterpret_cast<const float2*>(p1);
                o0 += c0.x; o1 += c0.y; o2 += c1.x; o3 += c1.y;
            }
            *reinterpret_cast<float2*>(p0) = make_float2(o0, o1);
            *reinterpret_cast<float2*>(p1) = make_float2(o2, o3);
        }
    }
}

// ---------------- Tensor-core flash attention --------------------------------
// 128 q-rows per CTA, 8 warps (16 rows each), 64-key tiles, tf32 mma.sync.
#define BQ 128
#define BKV 64
#define KST 68     // smem stride (floats): (68*g + tk) % 32 = 4g+tk -> conflict-free
#define ATT_SMEM ((2 * BQ * KST + 4 * BKV * KST) * 4)   // Q + P + 2x(K,V) = 139264 B

__global__ __launch_bounds__(256, 1) void flash_attn_tc(
    const float* __restrict__ qkv, float* __restrict__ att)
{
    extern __shared__ float smd[];
    float* Qs  = smd;                    // [BQ][KST]
    float* Ps  = Qs + BQ * KST;          // [BQ][KST]
    float* KV0 = Ps + BQ * KST;          // 2 buffers x (K[64][KST], V[64][KST])

    const int qb = gridDim.x - 1 - blockIdx.x;   // heavy tiles first
    const int h  = blockIdx.y;
    const int q0 = qb * BQ;
    const int tid = threadIdx.x, lane = tid & 31, w = tid >> 5;
    const int g = lane >> 2, tk = lane & 3;
    const int ld = 3 * EE;
    const int qoff = h * HD;

    // Q tile -> smem
    for (int i = tid; i < BQ * HD / 4; i += 256) {
        int r = i >> 4, c4 = (i & 15) * 4;
        float4 v = *reinterpret_cast<const float4*>(qkv + (size_t)(q0 + r) * ld + qoff + c4);
        *reinterpret_cast<float4*>(Qs + r * KST + c4) = v;
    }

    auto loadKV = [&](int buf, int k0) {
        float* Kd = KV0 + buf * 2 * BKV * KST;
        uint32_t kda = smem_u32(Kd);
        uint32_t vda = kda + BKV * KST * 4;
        #pragma unroll
        for (int i = 0; i < 4; i++) {
            int q = tid + 256 * i;
            int r = q >> 4, c4 = (q & 15) * 4;
            CP16(kda + (uint32_t)(r * KST + c4) * 4,
                 qkv + (size_t)(k0 + r) * ld + EE + qoff + c4);
            CP16(vda + (uint32_t)(r * KST + c4) * 4,
                 qkv + (size_t)(k0 + r) * ld + 2 * EE + qoff + c4);
        }
        CP_COMMIT();
    };

    const int kbmax = (q0 + BQ - 1) >> 6;   // inclusive
    loadKV(0, 0);

    float O[8][4];
    float mrow[2] = { -1e30f, -1e30f };
    float lrow[2] = { 0.f, 0.f };
    #pragma unroll
    for (int nt = 0; nt < 8; nt++)
        #pragma unroll
        for (int i = 0; i < 4; i++) O[nt][i] = 0.f;

    float* Pw = Ps + (w * 16) * KST;
    const float* Aq = Qs + (w * 16) * KST;

    for (int kb = 0; kb <= kbmax; kb++) {
        const int buf = kb & 1;
        if (kb < kbmax) { loadKV(buf ^ 1, (kb + 1) * BKV); CP_WAIT(1); }
        else            { CP_WAIT(0); }
        __syncthreads();

        const float* Ks = KV0 + buf * 2 * BKV * KST;
        const float* Vs = Ks + BKV * KST;
        const int k0 = kb * BKV;

        // ---- S = Q @ K^T (warp: 16 x 64) ----
        float S[8][4];
        #pragma unroll
        for (int nt = 0; nt < 8; nt++)
            #pragma unroll
            for (int i = 0; i < 4; i++) S[nt][i] = 0.f;

        #pragma unroll
        for (int kk = 0; kk < 8; kk++) {
            const int kc = kk * 8;
            uint32_t a[4];
            a[0] = f2tf32(Aq[(g    ) * KST + kc + tk    ]);
            a[1] = f2tf32(Aq[(g + 8) * KST + kc + tk    ]);
            a[2] = f2tf32(Aq[(g    ) * KST + kc + tk + 4]);
            a[3] = f2tf32(Aq[(g + 8) * KST + kc + tk + 4]);
            #pragma unroll
            for (int nt = 0; nt < 8; nt++) {
                uint32_t b[2];
                b[0] = f2tf32(Ks[(nt * 8 + g) * KST + kc + tk    ]);
                b[1] = f2tf32(Ks[(nt * 8 + g) * KST + kc + tk + 4]);
                mma_tf32(S[nt], a, b);
            }
        }

        // ---- scale + causal mask + online softmax (2 rows/thread) ----
        #pragma unroll
        for (int hf = 0; hf < 2; hf++) {
            const int gq = q0 + w * 16 + g + hf * 8;
            #pragma unroll
            for (int nt = 0; nt < 8; nt++) {
                const int gk = k0 + nt * 8 + 2 * tk;
                float s0 = S[nt][hf*2]   * 0.125f;
                float s1 = S[nt][hf*2+1] * 0.125f;
                S[nt][hf*2]   = (gk     <= gq) ? s0 : -10000.0f;
                S[nt][hf*2+1] = (gk + 1 <= gq) ? s1 : -10000.0f;
            }
            float rm = -1e30f;
            #pragma unroll
            for (int nt = 0; nt < 8; nt++)
                rm = fmaxf(rm, fmaxf(S[nt][hf*2], S[nt][hf*2+1]));
            rm = fmaxf(rm, __shfl_xor_sync(0xffffffffu, rm, 1));
            rm = fmaxf(rm, __shfl_xor_sync(0xffffffffu, rm, 2));
            const float mn = fmaxf(mrow[hf], rm);
            const float corr = __expf(mrow[hf] - mn);
            mrow[hf] = mn;
            float rs = 0.f;
            #pragma unroll
            for (int nt = 0; nt < 8; nt++) {
                float p0 = __expf(S[nt][hf*2]   - mn);
                float p1 = __expf(S[nt][hf*2+1] - mn);
                S[nt][hf*2] = p0; S[nt][hf*2+1] = p1;
                rs += p0 + p1;
            }
            rs += __shfl_xor_sync(0xffffffffu, rs, 1);
            rs += __shfl_xor_sync(0xffffffffu, rs, 2);
            lrow[hf] = lrow[hf] * corr + rs;
            #pragma unroll
            for (int nt = 0; nt < 8; nt++) {
                O[nt][hf*2] *= corr; O[nt][hf*2+1] *= corr;
            }
        }

        // ---- stage P (per-warp region) ----
        #pragma unroll
        for (int nt = 0; nt < 8; nt++) {
            *reinterpret_cast<float2*>(Pw + (g    ) * KST + nt * 8 + 2 * tk) =
                make_float2(S[nt][0], S[nt][1]);
            *reinterpret_cast<float2*>(Pw + (g + 8) * KST + nt * 8 + 2 * tk) =
                make_float2(S[nt][2], S[nt][3]);
        }
        __syncwarp();

        // ---- O += P @ V (warp: 16 x 64, K-dim = 64 keys) ----
        #pragma unroll
        for (int kk = 0; kk < 8; kk++) {
            const int kc = kk * 8;
            uint32_t a[4];
            a[0] = f2tf32(Pw[(g    ) * KST + kc + tk    ]);
            a[1] = f2tf32(Pw[(g + 8) * KST + kc + tk    ]);
            a[2] = f2tf32(Pw[(g    ) * KST + kc + tk + 4]);
            a[3] = f2tf32(Pw[(g + 8) * KST + kc + tk + 4]);
            #pragma unroll
            for (int nt = 0; nt < 8; nt++) {
                uint32_t b[2];
                b[0] = f2tf32(Vs[(kc + tk    ) * KST + nt * 8 + g]);
                b[1] = f2tf32(Vs[(kc + tk + 4) * KST + nt * 8 + g]);
                mma_tf32(O[nt], a, b);
            }
        }
        __syncthreads();   // buffer + P reuse guard
    }

    const float inv0 = 1.0f / lrow[0];
    const float inv1 = 1.0f / lrow[1];
    const int r0 = q0 + w * 16 + g;
    #pragma unroll
    for (int nt = 0; nt < 8; nt++) {
        const int col = qoff + nt * 8 + 2 * tk;
        *reinterpret_cast<float2*>(att + (size_t)r0 * EE + col) =
            make_float2(O[nt][0] * inv0, O[nt][1] * inv0);
        *reinterpret_cast<float2*>(att + (size_t)(r0 + 8) * EE + col) =
            make_float2(O[nt][2] * inv1, O[nt][3] * inv1);
    }
}

// ---------------- host orchestration ---------------------------------------
extern "C" void kernel_launch(void* const* d_in, const int* in_sizes, int n_in,
                              void* d_out, int out_size)
{
    const float* x      = (const float*)d_in[0];
    const float* ln1_w  = (const float*)d_in[1];
    const float* ln1_b  = (const float*)d_in[2];
    const float* attn_w = (const float*)d_in[3];
    const float* attn_b = (const float*)d_in[4];
    const float* proj_w = (const float*)d_in[5];
    const float* proj_b = (const float*)d_in[6];
    const float* ln2_w  = (const float*)d_in[7];
    const float* ln2_b  = (const float*)d_in[8];
    const float* fc_w   = (const float*)d_in[9];
    const float* fc_b   = (const float*)d_in[10];
    const float* fc2_w  = (const float*)d_in[11];
    const float* fc2_b  = (const float*)d_in[12];

    float *h, *y, *qkv, *att, *m1;
    cudaGetSymbolAddress((void**)&h,   g_h);
    cudaGetSymbolAddress((void**)&y,   g_y);
    cudaGetSymbolAddress((void**)&qkv, g_qkv);
    cudaGetSymbolAddress((void**)&att, g_att);
    cudaGetSymbolAddress((void**)&m1,  g_m1);

    constexpr int SMEM_128 = (A_SZ + 32 * (128 + 8)) * 2 * 4;
    constexpr int SMEM_64  = (A_SZ + 32 * ( 64 + 8)) * 2 * 4;
    cudaFuncSetAttribute(mma_gemm<0,128>, cudaFuncAttributeMaxDynamicSharedMemorySize, SMEM_128);
    cudaFuncSetAttribute(mma_gemm<1,128>, cudaFuncAttributeMaxDynamicSharedMemorySize, SMEM_128);
    cudaFuncSetAttribute(mma_gemm<2,64>,  cudaFuncAttributeMaxDynamicSharedMemorySize, SMEM_64);
    cudaFuncSetAttribute(flash_attn_tc,   cudaFuncAttributeMaxDynamicSharedMemorySize, ATT_SMEM);

    cudaMemcpyAsync(h, x, (size_t)TT * EE * sizeof(float),
                    cudaMemcpyDeviceToDevice, 0);

    const dim3 blk(256);
    const dim3 gLN(TT);
    const dim3 gQKV(3 * EE / 128, TT / 128);   // (24,16)
    const dim3 gPROJ(EE / 64, TT / 128);       // (16,16)
    const dim3 gFC(4 * EE / 128, TT / 128);    // (32,16)
    const dim3 gFC2(EE / 64, TT / 128);        // (16,16)
    const dim3 gATT(TT / BQ, NH);              // (16,16)

    for (int lyr = 0; lyr < NL; lyr++) {
        const float* aw  = attn_w + (size_t)lyr * EE * 3 * EE;
        const float* ab  = attn_b + (size_t)lyr * 3 * EE;
        const float* pw  = proj_w + (size_t)lyr * EE * EE;
        const float* pb  = proj_b + (size_t)lyr * EE;
        const float* fw  = fc_w   + (size_t)lyr * EE * 4 * EE;
        const float* fb  = fc_b   + (size_t)lyr * 4 * EE;
        const float* f2w = fc2_w  + (size_t)lyr * 4 * EE * EE;
        const float* f2b = fc2_b  + (size_t)lyr * EE;

        // attn block
        ln_kernel<<<gLN, blk>>>(h, ln1_w + (size_t)lyr * EE, ln1_b + (size_t)lyr * EE, y);
        mma_gemm<0,128><<<gQKV, blk, SMEM_128>>>(y, aw, ab, qkv, TT, 3 * EE, EE);
        flash_attn_tc<<<gATT, blk, ATT_SMEM>>>(qkv, att);
        mma_gemm<2,64><<<gPROJ, blk, SMEM_64>>>(att, pw, pb, h, TT, EE, EE);

        // MLP block
        ln_kernel<<<gLN, blk>>>(h, ln2_w + (size_t)lyr * EE, ln2_b + (size_t)lyr * EE, y);
        mma_gemm<1,128><<<gFC, blk, SMEM_128>>>(y, fw, fb, m1, TT, 4 * EE, EE);
        mma_gemm<2,64><<<gFC2, blk, SMEM_64>>>(m1, f2w, f2b, h, TT, EE, 4 * EE);
    }

    cudaMemcpyAsync(d_out, h, (size_t)TT * EE * sizeof(float),
                    cudaMemcpyDeviceToDevice, 0);
}

// round 6
// speedup vs baseline: 1.4871x; 1.0396x over previous
#include <cuda_runtime.h>
#include <math.h>
#include <stdint.h>

// GPT-2 stack: L=8, E=1024, H=16, T=2048, B=1, DH=64, fp32 in/out.
#define TT 2048
#define EE 1024
#define NH 16
#define HD 64
#define NL 8

// ---------------- scratch (device globals; no allocation allowed) ----------
__device__ float g_h  [TT * EE];        // residual stream (plain fp32)
__device__ float g_y  [TT * EE];        // LN output (tf32-rounded, k-permuted)
__device__ float g_qkv[TT * 3 * EE];    // QKV (tf32-rounded, plain layout)
__device__ float g_att[TT * EE];        // attention out (rounded, permuted)
__device__ float g_m1 [TT * 4 * EE];    // MLP hidden (rounded, permuted)

// transposed + tf32-rounded + k-permuted weights: wT[n][perm(k)]
__device__ float g_wqkvT[NL * 3 * EE * EE];
__device__ float g_wprojT[NL * EE * EE];
__device__ float g_wfcT [NL * 4 * EE * EE];
__device__ float g_wfc2T[NL * EE * 4 * EE];

// ---------------- helpers ----------------------------------------------------
__device__ __forceinline__ uint32_t f2tf32(float x) {
    uint32_t r;
    asm("cvt.rna.tf32.f32 %0, %1;" : "=r"(r) : "f"(x));
    return r;
}
__device__ __forceinline__ float roundtf32(float x) {
    return __uint_as_float(f2tf32(x));
}
// k-permutation within 32-blocks: position p holds logical column k, p=perm32(k)
__device__ __forceinline__ int perm32(int c) {
    return (c & ~31) | ((c & 3) << 3) | (((c >> 3) & 3) << 1) | ((c >> 2) & 1);
}
__device__ __forceinline__ uint32_t smem_u32(const void* p) {
    return (uint32_t)__cvta_generic_to_shared(p);
}
__device__ __forceinline__ void mma_tf32(float c[4], const uint32_t a[4], const uint32_t b[2]) {
    asm volatile(
        "mma.sync.aligned.m16n8k8.row.col.f32.tf32.tf32.f32 "
        "{%0,%1,%2,%3}, {%4,%5,%6,%7}, {%8,%9}, {%0,%1,%2,%3};\n"
        : "+f"(c[0]), "+f"(c[1]), "+f"(c[2]), "+f"(c[3])
        : "r"(a[0]), "r"(a[1]), "r"(a[2]), "r"(a[3]),
          "r"(b[0]), "r"(b[1]));
}
#define CP16(dst, src) asm volatile("cp.async.cg.shared.global [%0], [%1], 16;\n" :: "r"(dst), "l"(src))
#define CP_COMMIT()    asm volatile("cp.async.commit_group;\n")
#define CP_WAIT(n)     asm volatile("cp.async.wait_group %0;\n" :: "n"(n))

__device__ __forceinline__ float gelu_tanh(float x) {
    const float c0 = 0.7978845608028654f;   // sqrt(2/pi)
    float t = tanhf(c0 * (x + 0.044715f * x * x * x));
    return 0.5f * x * (1.0f + t);
}

// ---------------- transpose + round + permute weights ------------------------
// src: [K][N] row-major per layer -> dst: [N][perm(K)] row-major per layer.
__global__ __launch_bounds__(256) void transpose_round_kernel(
    const float* __restrict__ src, float* __restrict__ dst, int K, int N)
{
    __shared__ float tile[32][33];
    const float* s = src + (size_t)blockIdx.z * K * N;
    float* d = dst + (size_t)blockIdx.z * K * N;
    const int k0 = blockIdx.y * 32, n0 = blockIdx.x * 32;
    const int tx = threadIdx.x, ty = threadIdx.y;   // 32 x 8
    #pragma unroll
    for (int i = 0; i < 32; i += 8)
        tile[ty + i][tx] = s[(size_t)(k0 + ty + i) * N + n0 + tx];
    __syncthreads();
    const int kp = ((tx & 3) << 3) | (((tx >> 3) & 3) << 1) | ((tx >> 2) & 1);
    #pragma unroll
    for (int i = 0; i < 32; i += 8)
        d[(size_t)(n0 + ty + i) * K + k0 + kp] = roundtf32(tile[tx][ty + i]);
}

// ---------------- LayerNorm: one block per token row ------------------------
// Output is tf32-rounded AND k-permuted (it is only consumed as GEMM A).
__global__ __launch_bounds__(256) void ln_kernel(
    const float* __restrict__ h, const float* __restrict__ w,
    const float* __restrict__ b, float* __restrict__ y)
{
    const int row = blockIdx.x;
    const int tid = threadIdx.x;
    const float4* hr = reinterpret_cast<const float4*>(h + (size_t)row * EE);
    float4 v = hr[tid];
    float s  = v.x + v.y + v.z + v.w;
    float sq = v.x*v.x + v.y*v.y + v.z*v.z + v.w*v.w;

    __shared__ float ss[8], ssq[8];
    #pragma unroll
    for (int off = 16; off > 0; off >>= 1) {
        s  += __shfl_xor_sync(0xffffffffu, s,  off);
        sq += __shfl_xor_sync(0xffffffffu, sq, off);
    }
    int lane = tid & 31, wid = tid >> 5;
    if (lane == 0) { ss[wid] = s; ssq[wid] = sq; }
    __syncthreads();
    if (tid == 0) {
        float S = 0.f, Q = 0.f;
        #pragma unroll
        for (int i = 0; i < 8; i++) { S += ss[i]; Q += ssq[i]; }
        ss[0] = S; ssq[0] = Q;
    }
    __syncthreads();
    const float mu  = ss[0] * (1.0f / EE);
    const float var = ssq[0] * (1.0f / EE) - mu * mu;
    const float inv = rsqrtf(var + 1e-5f);

    float4 wv = reinterpret_cast<const float4*>(w)[tid];
    float4 bv = reinterpret_cast<const float4*>(b)[tid];
    float o[4];
    o[0] = roundtf32((v.x - mu) * inv * wv.x + bv.x);
    o[1] = roundtf32((v.y - mu) * inv * wv.y + bv.y);
    o[2] = roundtf32((v.z - mu) * inv * wv.z + bv.z);
    o[3] = roundtf32((v.w - mu) * inv * wv.w + bv.w);
    float* yr = y + (size_t)row * EE;
    const int e = tid * 4;
    #pragma unroll
    for (int j = 0; j < 4; j++) yr[perm32(e + j)] = o[j];
}

// ---------------- TF32 tensor-core GEMM (mma.sync, vector fragments) ---------
// A [M,K]: tf32-rounded + k-permuted.  Bt [N,K]: transposed + rounded + permuted.
// MODE 0: round(x+bias), plain layout (qkv -> attention)
// MODE 1: round(gelu(x+bias)), permuted layout (m1 -> fc2 A)
// MODE 2: C += x + bias, plain fp32 (residual)
template <int MODE, int BN>
__global__ __launch_bounds__(256, 2) void mma_gemm(
    const float* __restrict__ A, const float* __restrict__ Bt,
    const float* __restrict__ bias, float* __restrict__ C,
    int M, int N, int K)
{
    constexpr int NT  = BN / 16;
    constexpr int ASZ = 128 * 36;
    constexpr int BSZ = BN * 36;

    extern __shared__ float sm[];
    float* Abuf[2] = { sm,       sm + ASZ + BSZ };
    float* Bbuf[2] = { sm + ASZ, sm + 2*ASZ + BSZ };

    const int tid  = threadIdx.x;
    const int lane = tid & 31;
    const int warp = tid >> 5;
    const int wm   = (warp & 3) * 32;
    const int wn   = (warp >> 2) * (BN / 2);
    const int g    = lane >> 2;
    const int tk   = lane & 3;

    const int bm = blockIdx.y * 128;
    const int bn = blockIdx.x * BN;

    uint32_t a_s[2], b_s[2];
    a_s[0] = smem_u32(Abuf[0]); a_s[1] = smem_u32(Abuf[1]);
    b_s[0] = smem_u32(Bbuf[0]); b_s[1] = smem_u32(Bbuf[1]);

    float acc[2][NT][4];
    #pragma unroll
    for (int mt = 0; mt < 2; mt++)
        #pragma unroll
        for (int nt = 0; nt < NT; nt++)
            #pragma unroll
            for (int i = 0; i < 4; i++) acc[mt][nt][i] = 0.f;

    auto load_tile = [&](int buf, int k0) {
        #pragma unroll
        for (int i = 0; i < 4; i++) {
            int idx = tid + 256 * i;
            int r = idx >> 3, c = (idx & 7) * 4;
            CP16(a_s[buf] + (uint32_t)(r * 36 + c) * 4,
                 A + (size_t)(bm + r) * K + k0 + c);
        }
        #pragma unroll
        for (int i = 0; i < BN / 32; i++) {
            int idx = tid + 256 * i;
            int r = idx >> 3, c = (idx & 7) * 4;
            CP16(b_s[buf] + (uint32_t)(r * 36 + c) * 4,
                 Bt + (size_t)(bn + r) * K + k0 + c);
        }
        CP_COMMIT();
    };

    const int nk = K / 32;
    load_tile(0, 0);

    for (int t = 0; t < nk; t++) {
        const int buf = t & 1;
        if (t + 1 < nk) {
            load_tile(buf ^ 1, (t + 1) * 32);
            CP_WAIT(1);
        } else {
            CP_WAIT(0);
        }
        __syncthreads();

        const float* Ab = Abuf[buf];
        const float* Bb = Bbuf[buf];

        #pragma unroll
        for (int h2 = 0; h2 < 2; h2++) {
            uint4 aq[2][2];
            #pragma unroll
            for (int mt = 0; mt < 2; mt++) {
                const float* pa = Ab + (wm + mt * 16 + g) * 36 + tk * 8 + h2 * 4;
                aq[mt][0] = *reinterpret_cast<const uint4*>(pa);
                aq[mt][1] = *reinterpret_cast<const uint4*>(pa + 8 * 36);
            }
            #pragma unroll
            for (int ng = 0; ng < NT / 4; ng++) {
                uint4 bq[4];
                #pragma unroll
                for (int j = 0; j < 4; j++) {
                    int nt = ng * 4 + j;
                    bq[j] = *reinterpret_cast<const uint4*>(
                        Bb + (wn + nt * 8 + g) * 36 + tk * 8 + h2 * 4);
                }
                #pragma unroll
                for (int ks = 0; ks < 2; ks++) {
                    #pragma unroll
                    for (int mt = 0; mt < 2; mt++) {
                        const uint32_t* q0 = reinterpret_cast<const uint32_t*>(&aq[mt][0]);
                        const uint32_t* q1 = reinterpret_cast<const uint32_t*>(&aq[mt][1]);
                        uint32_t a[4] = { q0[2*ks], q1[2*ks], q0[2*ks+1], q1[2*ks+1] };
                        #pragma unroll
                        for (int j = 0; j < 4; j++) {
                            const uint32_t* qb = reinterpret_cast<const uint32_t*>(&bq[j]);
                            uint32_t b[2] = { qb[2*ks], qb[2*ks+1] };
                            mma_tf32(acc[mt][ng*4+j], a, b);
                        }
                    }
                }
            }
        }
        __syncthreads();
    }

    #pragma unroll
    for (int mt = 0; mt < 2; mt++) {
        const int row0 = bm + wm + mt * 16 + g;
        #pragma unroll
        for (int nt = 0; nt < NT; nt++) {
            const int col = bn + wn + nt * 8 + 2 * tk;
            float2 bv = *reinterpret_cast<const float2*>(bias + col);
            float o0 = acc[mt][nt][0] + bv.x;
            float o1 = acc[mt][nt][1] + bv.y;
            float o2 = acc[mt][nt][2] + bv.x;
            float o3 = acc[mt][nt][3] + bv.y;
            if (MODE == 0) {
                o0 = roundtf32(o0); o1 = roundtf32(o1);
                o2 = roundtf32(o2); o3 = roundtf32(o3);
                *reinterpret_cast<float2*>(C + (size_t)row0 * N + col)       = make_float2(o0, o1);
                *reinterpret_cast<float2*>(C + (size_t)(row0 + 8) * N + col) = make_float2(o2, o3);
            } else if (MODE == 1) {
                o0 = roundtf32(gelu_tanh(o0)); o1 = roundtf32(gelu_tanh(o1));
                o2 = roundtf32(gelu_tanh(o2)); o3 = roundtf32(gelu_tanh(o3));
                const int p0 = perm32(col), p1 = perm32(col + 1);
                C[(size_t)row0 * N + p0] = o0;
                C[(size_t)row0 * N + p1] = o1;
                C[(size_t)(row0 + 8) * N + p0] = o2;
                C[(size_t)(row0 + 8) * N + p1] = o3;
            } else {
                float* p0 = C + (size_t)row0 * N + col;
                float* p1 = C + (size_t)(row0 + 8) * N + col;
                float2 c0 = *reinterpret_cast<const float2*>(p0);
                float2 c1 = *reinterpret_cast<const float2*>(p1);
                *reinterpret_cast<float2*>(p0) = make_float2(o0 + c0.x, o1 + c0.y);
                *reinterpret_cast<float2*>(p1) = make_float2(o2 + c1.x, o3 + c1.y);
            }
        }
    }
}

// ---------------- Tensor-core flash attention --------------------------------
// Inputs (q,k,v) are tf32-pre-rounded by the qkv GEMM epilogue -> no cvt needed.
#define BQ 128
#define BKV 64
#define KST 68
#define ATT_SMEM ((2 * BQ * KST + 4 * BKV * KST) * 4)

__global__ __launch_bounds__(256, 1) void flash_attn_tc(
    const float* __restrict__ qkv, float* __restrict__ att)
{
    extern __shared__ float smd[];
    float* Qs  = smd;
    float* Ps  = Qs + BQ * KST;
    float* KV0 = Ps + BQ * KST;

    const int qb = gridDim.x - 1 - blockIdx.x;
    const int h  = blockIdx.y;
    const int q0 = qb * BQ;
    const int tid = threadIdx.x, lane = tid & 31, w = tid >> 5;
    const int g = lane >> 2, tk = lane & 3;
    const int ld = 3 * EE;
    const int qoff = h * HD;

    for (int i = tid; i < BQ * HD / 4; i += 256) {
        int r = i >> 4, c4 = (i & 15) * 4;
        float4 v = *reinterpret_cast<const float4*>(qkv + (size_t)(q0 + r) * ld + qoff + c4);
        *reinterpret_cast<float4*>(Qs + r * KST + c4) = v;
    }

    auto loadKV = [&](int buf, int k0) {
        float* Kd = KV0 + buf * 2 * BKV * KST;
        uint32_t kda = smem_u32(Kd);
        uint32_t vda = kda + BKV * KST * 4;
        #pragma unroll
        for (int i = 0; i < 4; i++) {
            int q = tid + 256 * i;
            int r = q >> 4, c4 = (q & 15) * 4;
            CP16(kda + (uint32_t)(r * KST + c4) * 4,
                 qkv + (size_t)(k0 + r) * ld + EE + qoff + c4);
            CP16(vda + (uint32_t)(r * KST + c4) * 4,
                 qkv + (size_t)(k0 + r) * ld + 2 * EE + qoff + c4);
        }
        CP_COMMIT();
    };

    const int kbmax = (q0 + BQ - 1) >> 6;
    loadKV(0, 0);

    float O[8][4];
    float mrow[2] = { -1e30f, -1e30f };
    float lrow[2] = { 0.f, 0.f };
    #pragma unroll
    for (int nt = 0; nt < 8; nt++)
        #pragma unroll
        for (int i = 0; i < 4; i++) O[nt][i] = 0.f;

    float* Pw = Ps + (w * 16) * KST;
    const float* Aq = Qs + (w * 16) * KST;

    for (int kb = 0; kb <= kbmax; kb++) {
        const int buf = kb & 1;
        if (kb < kbmax) { loadKV(buf ^ 1, (kb + 1) * BKV); CP_WAIT(1); }
        else            { CP_WAIT(0); }
        __syncthreads();

        const float* Ks = KV0 + buf * 2 * BKV * KST;
        const float* Vs = Ks + BKV * KST;
        const int k0 = kb * BKV;

        float S[8][4];
        #pragma unroll
        for (int nt = 0; nt < 8; nt++)
            #pragma unroll
            for (int i = 0; i < 4; i++) S[nt][i] = 0.f;

        #pragma unroll
        for (int kk = 0; kk < 8; kk++) {
            const int kc = kk * 8;
            uint32_t a[4];
            a[0] = __float_as_uint(Aq[(g    ) * KST + kc + tk    ]);
            a[1] = __float_as_uint(Aq[(g + 8) * KST + kc + tk    ]);
            a[2] = __float_as_uint(Aq[(g    ) * KST + kc + tk + 4]);
            a[3] = __float_as_uint(Aq[(g + 8) * KST + kc + tk + 4]);
            #pragma unroll
            for (int nt = 0; nt < 8; nt++) {
                uint32_t b[2];
                b[0] = __float_as_uint(Ks[(nt * 8 + g) * KST + kc + tk    ]);
                b[1] = __float_as_uint(Ks[(nt * 8 + g) * KST + kc + tk + 4]);
                mma_tf32(S[nt], a, b);
            }
        }

        #pragma unroll
        for (int hf = 0; hf < 2; hf++) {
            const int gq = q0 + w * 16 + g + hf * 8;
            #pragma unroll
            for (int nt = 0; nt < 8; nt++) {
                const int gk = k0 + nt * 8 + 2 * tk;
                float s0 = S[nt][hf*2]   * 0.125f;
                float s1 = S[nt][hf*2+1] * 0.125f;
                S[nt][hf*2]   = (gk     <= gq) ? s0 : -10000.0f;
                S[nt][hf*2+1] = (gk + 1 <= gq) ? s1 : -10000.0f;
            }
            float rm = -1e30f;
            #pragma unroll
            for (int nt = 0; nt < 8; nt++)
                rm = fmaxf(rm, fmaxf(S[nt][hf*2], S[nt][hf*2+1]));
            rm = fmaxf(rm, __shfl_xor_sync(0xffffffffu, rm, 1));
            rm = fmaxf(rm, __shfl_xor_sync(0xffffffffu, rm, 2));
            const float mn = fmaxf(mrow[hf], rm);
            const float corr = __expf(mrow[hf] - mn);
            mrow[hf] = mn;
            float rs = 0.f;
            #pragma unroll
            for (int nt = 0; nt < 8; nt++) {
                float p0 = __expf(S[nt][hf*2]   - mn);
                float p1 = __expf(S[nt][hf*2+1] - mn);
                S[nt][hf*2] = p0; S[nt][hf*2+1] = p1;
                rs += p0 + p1;
            }
            rs += __shfl_xor_sync(0xffffffffu, rs, 1);
            rs += __shfl_xor_sync(0xffffffffu, rs, 2);
            lrow[hf] = lrow[hf] * corr + rs;
            #pragma unroll
            for (int nt = 0; nt < 8; nt++) {
                O[nt][hf*2] *= corr; O[nt][hf*2+1] *= corr;
            }
        }

        // stage P (tf32-pre-rounded so P@V loads are raw bits)
        #pragma unroll
        for (int nt = 0; nt < 8; nt++) {
            *reinterpret_cast<float2*>(Pw + (g    ) * KST + nt * 8 + 2 * tk) =
                make_float2(roundtf32(S[nt][0]), roundtf32(S[nt][1]));
            *reinterpret_cast<float2*>(Pw + (g + 8) * KST + nt * 8 + 2 * tk) =
                make_float2(roundtf32(S[nt][2]), roundtf32(S[nt][3]));
        }
        __syncwarp();

        #pragma unroll
        for (int kk = 0; kk < 8; kk++) {
            const int kc = kk * 8;
            uint32_t a[4];
            a[0] = __float_as_uint(Pw[(g    ) * KST + kc + tk    ]);
            a[1] = __float_as_uint(Pw[(g + 8) * KST + kc + tk    ]);
            a[2] = __float_as_uint(Pw[(g    ) * KST + kc + tk + 4]);
            a[3] = __float_as_uint(Pw[(g + 8) * KST + kc + tk + 4]);
            #pragma unroll
            for (int nt = 0; nt < 8; nt++) {
                uint32_t b[2];
                b[0] = __float_as_uint(Vs[(kc + tk    ) * KST + nt * 8 + g]);
                b[1] = __float_as_uint(Vs[(kc + tk + 4) * KST + nt * 8 + g]);
                mma_tf32(O[nt], a, b);
            }
        }
        __syncthreads();
    }

    // output: rounded + k-permuted (att only feeds proj GEMM A)
    const float inv0 = 1.0f / lrow[0];
    const float inv1 = 1.0f / lrow[1];
    const int r0 = q0 + w * 16 + g;
    #pragma unroll
    for (int nt = 0; nt < 8; nt++) {
        const int col = qoff + nt * 8 + 2 * tk;
        const int p0 = perm32(col), p1 = perm32(col + 1);
        att[(size_t)r0 * EE + p0] = roundtf32(O[nt][0] * inv0);
        att[(size_t)r0 * EE + p1] = roundtf32(O[nt][1] * inv0);
        att[(size_t)(r0 + 8) * EE + p0] = roundtf32(O[nt][2] * inv1);
        att[(size_t)(r0 + 8) * EE + p1] = roundtf32(O[nt][3] * inv1);
    }
}

// ---------------- host orchestration ---------------------------------------
extern "C" void kernel_launch(void* const* d_in, const int* in_sizes, int n_in,
                              void* d_out, int out_size)
{
    const float* x      = (const float*)d_in[0];
    const float* ln1_w  = (const float*)d_in[1];
    const float* ln1_b  = (const float*)d_in[2];
    const float* attn_w = (const float*)d_in[3];
    const float* attn_b = (const float*)d_in[4];
    const float* proj_w = (const float*)d_in[5];
    const float* proj_b = (const float*)d_in[6];
    const float* ln2_w  = (const float*)d_in[7];
    const float* ln2_b  = (const float*)d_in[8];
    const float* fc_w   = (const float*)d_in[9];
    const float* fc_b   = (const float*)d_in[10];
    const float* fc2_w  = (const float*)d_in[11];
    const float* fc2_b  = (const float*)d_in[12];

    float *h, *y, *qkv, *att, *m1, *wqkvT, *wprojT, *wfcT, *wfc2T;
    cudaGetSymbolAddress((void**)&h,     g_h);
    cudaGetSymbolAddress((void**)&y,     g_y);
    cudaGetSymbolAddress((void**)&qkv,   g_qkv);
    cudaGetSymbolAddress((void**)&att,   g_att);
    cudaGetSymbolAddress((void**)&m1,    g_m1);
    cudaGetSymbolAddress((void**)&wqkvT, g_wqkvT);
    cudaGetSymbolAddress((void**)&wprojT,g_wprojT);
    cudaGetSymbolAddress((void**)&wfcT,  g_wfcT);
    cudaGetSymbolAddress((void**)&wfc2T, g_wfc2T);

    constexpr int SMEM_128 = (128 * 36 + 128 * 36) * 2 * 4;   // 73728
    constexpr int SMEM_64  = (128 * 36 +  64 * 36) * 2 * 4;   // 55296
    cudaFuncSetAttribute(mma_gemm<0,128>, cudaFuncAttributeMaxDynamicSharedMemorySize, SMEM_128);
    cudaFuncSetAttribute(mma_gemm<1,128>, cudaFuncAttributeMaxDynamicSharedMemorySize, SMEM_128);
    cudaFuncSetAttribute(mma_gemm<2,64>,  cudaFuncAttributeMaxDynamicSharedMemorySize, SMEM_64);
    cudaFuncSetAttribute(flash_attn_tc,   cudaFuncAttributeMaxDynamicSharedMemorySize, ATT_SMEM);

    // transpose + round + permute all weights once per replay
    const dim3 tb(32, 8);
    transpose_round_kernel<<<dim3(3*EE/32, EE/32, NL),   tb>>>(attn_w, wqkvT,  EE,   3*EE);
    transpose_round_kernel<<<dim3(EE/32,   EE/32, NL),   tb>>>(proj_w, wprojT, EE,   EE);
    transpose_round_kernel<<<dim3(4*EE/32, EE/32, NL),   tb>>>(fc_w,   wfcT,   EE,   4*EE);
    transpose_round_kernel<<<dim3(EE/32,   4*EE/32, NL), tb>>>(fc2_w,  wfc2T,  4*EE, EE);

    cudaMemcpyAsync(h, x, (size_t)TT * EE * sizeof(float),
                    cudaMemcpyDeviceToDevice, 0);

    const dim3 blk(256);
    const dim3 gLN(TT);
    const dim3 gQKV(3 * EE / 128, TT / 128);   // (24,16)
    const dim3 gPROJ(EE / 64, TT / 128);       // (16,16)
    const dim3 gFC(4 * EE / 128, TT / 128);    // (32,16)
    const dim3 gFC2(EE / 64, TT / 128);        // (16,16)
    const dim3 gATT(TT / BQ, NH);              // (16,16)

    for (int lyr = 0; lyr < NL; lyr++) {
        const float* aw  = wqkvT  + (size_t)lyr * EE * 3 * EE;
        const float* ab  = attn_b + (size_t)lyr * 3 * EE;
        const float* pw  = wprojT + (size_t)lyr * EE * EE;
        const float* pb  = proj_b + (size_t)lyr * EE;
        const float* fw  = wfcT   + (size_t)lyr * EE * 4 * EE;
        const float* fb  = fc_b   + (size_t)lyr * 4 * EE;
        const float* f2w = wfc2T  + (size_t)lyr * 4 * EE * EE;
        const float* f2b = fc2_b  + (size_t)lyr * EE;

        // attn block
        ln_kernel<<<gLN, blk>>>(h, ln1_w + (size_t)lyr * EE, ln1_b + (size_t)lyr * EE, y);
        mma_gemm<0,128><<<gQKV, blk, SMEM_128>>>(y, aw, ab, qkv, TT, 3 * EE, EE);
        flash_attn_tc<<<gATT, blk, ATT_SMEM>>>(qkv, att);
        mma_gemm<2,64><<<gPROJ, blk, SMEM_64>>>(att, pw, pb, h, TT, EE, EE);

        // MLP block
        ln_kernel<<<gLN, blk>>>(h, ln2_w + (size_t)lyr * EE, ln2_b + (size_t)lyr * EE, y);
        mma_gemm<1,128><<<gFC, blk, SMEM_128>>>(y, fw, fb, m1, TT, 4 * EE, EE);
        mma_gemm<2,64><<<gFC2, blk, SMEM_64>>>(m1, f2w, f2b, h, TT, EE, 4 * EE);
    }

    cudaMemcpyAsync(d_out, h, (size_t)TT * EE * sizeof(float),
                    cudaMemcpyDeviceToDevice, 0);
}

// round 7
// speedup vs baseline: 3.0948x; 2.0810x over previous
#include <cuda_runtime.h>
#include <cuda_fp16.h>
#include <math.h>
#include <stdint.h>

// GPT-2 stack: L=8, E=1024, H=16, T=2048, B=1, DH=64, fp32 in/out.
#define TT 2048
#define EE 1024
#define NH 16
#define HD 64
#define NL 8

// ---------------- scratch (device globals; no allocation allowed) ----------
__device__ float  g_h  [TT * EE];        // residual stream (fp32)
__device__ __half g_y  [TT * EE];        // LN output (fp16)
__device__ __half g_qkv[TT * 3 * EE];    // QKV (fp16)
__device__ __half g_att[TT * EE];        // attention output (fp16)
__device__ __half g_m1 [TT * 4 * EE];    // MLP hidden (fp16)

// transposed fp16 weights: wT[n][k]
__device__ __half g_wqkvT[NL * 3 * EE * EE];
__device__ __half g_wprojT[NL * EE * EE];
__device__ __half g_wfcT [NL * 4 * EE * EE];
__device__ __half g_wfc2T[NL * EE * 4 * EE];

// ---------------- helpers ----------------------------------------------------
__device__ __forceinline__ uint32_t smem_u32(const void* p) {
    return (uint32_t)__cvta_generic_to_shared(p);
}
__device__ __forceinline__ void mma_f16(float c[4], const uint32_t a[4],
                                        uint32_t b0, uint32_t b1) {
    asm volatile(
        "mma.sync.aligned.m16n8k16.row.col.f32.f16.f16.f32 "
        "{%0,%1,%2,%3}, {%4,%5,%6,%7}, {%8,%9}, {%0,%1,%2,%3};\n"
        : "+f"(c[0]), "+f"(c[1]), "+f"(c[2]), "+f"(c[3])
        : "r"(a[0]), "r"(a[1]), "r"(a[2]), "r"(a[3]), "r"(b0), "r"(b1));
}
__device__ __forceinline__ uint4 ldmx4(uint32_t a) {
    uint4 r;
    asm volatile("ldmatrix.sync.aligned.m8n8.x4.shared.b16 {%0,%1,%2,%3}, [%4];"
        : "=r"(r.x), "=r"(r.y), "=r"(r.z), "=r"(r.w) : "r"(a));
    return r;
}
__device__ __forceinline__ uint2 ldmx2t(uint32_t a) {
    uint2 r;
    asm volatile("ldmatrix.sync.aligned.m8n8.x2.trans.shared.b16 {%0,%1}, [%2];"
        : "=r"(r.x), "=r"(r.y) : "r"(a));
    return r;
}
#define CP16(dst, src) asm volatile("cp.async.cg.shared.global [%0], [%1], 16;\n" :: "r"(dst), "l"(src))
#define CP_COMMIT()    asm volatile("cp.async.commit_group;\n")
#define CP_WAIT(n)     asm volatile("cp.async.wait_group %0;\n" :: "n"(n))

__device__ __forceinline__ float gelu_tanh(float x) {
    const float c0 = 0.7978845608028654f;   // sqrt(2/pi)
    float t = tanhf(c0 * (x + 0.044715f * x * x * x));
    return 0.5f * x * (1.0f + t);
}

// ---------------- transpose weights to fp16 [N][K] ---------------------------
__global__ __launch_bounds__(256) void transpose_half_kernel(
    const float* __restrict__ src, __half* __restrict__ dst, int K, int N)
{
    __shared__ float tile[32][33];
    const float* s = src + (size_t)blockIdx.z * K * N;
    __half* d = dst + (size_t)blockIdx.z * K * N;
    const int k0 = blockIdx.y * 32, n0 = blockIdx.x * 32;
    const int tx = threadIdx.x, ty = threadIdx.y;   // 32 x 8
    #pragma unroll
    for (int i = 0; i < 32; i += 8)
        tile[ty + i][tx] = s[(size_t)(k0 + ty + i) * N + n0 + tx];
    __syncthreads();
    #pragma unroll
    for (int i = 0; i < 32; i += 8)
        d[(size_t)(n0 + ty + i) * K + k0 + tx] = __float2half(tile[tx][ty + i]);
}

// ---------------- LayerNorm: one block per token row ------------------------
__global__ __launch_bounds__(256) void ln_kernel(
    const float* __restrict__ h, const float* __restrict__ w,
    const float* __restrict__ b, __half* __restrict__ y)
{
    const int row = blockIdx.x;
    const int tid = threadIdx.x;
    const float4* hr = reinterpret_cast<const float4*>(h + (size_t)row * EE);
    float4 v = hr[tid];
    float s  = v.x + v.y + v.z + v.w;
    float sq = v.x*v.x + v.y*v.y + v.z*v.z + v.w*v.w;

    __shared__ float ss[8], ssq[8];
    #pragma unroll
    for (int off = 16; off > 0; off >>= 1) {
        s  += __shfl_xor_sync(0xffffffffu, s,  off);
        sq += __shfl_xor_sync(0xffffffffu, sq, off);
    }
    int lane = tid & 31, wid = tid >> 5;
    if (lane == 0) { ss[wid] = s; ssq[wid] = sq; }
    __syncthreads();
    if (tid == 0) {
        float S = 0.f, Q = 0.f;
        #pragma unroll
        for (int i = 0; i < 8; i++) { S += ss[i]; Q += ssq[i]; }
        ss[0] = S; ssq[0] = Q;
    }
    __syncthreads();
    const float mu  = ss[0] * (1.0f / EE);
    const float var = ssq[0] * (1.0f / EE) - mu * mu;
    const float inv = rsqrtf(var + 1e-5f);

    float4 wv = reinterpret_cast<const float4*>(w)[tid];
    float4 bv = reinterpret_cast<const float4*>(b)[tid];
    __half2* yr = reinterpret_cast<__half2*>(y + (size_t)row * EE);
    yr[tid*2]   = __floats2half2_rn((v.x - mu) * inv * wv.x + bv.x,
                                    (v.y - mu) * inv * wv.y + bv.y);
    yr[tid*2+1] = __floats2half2_rn((v.z - mu) * inv * wv.z + bv.z,
                                    (v.w - mu) * inv * wv.w + bv.w);
}

// ---------------- fp16 tensor-core GEMM (mma.sync m16n8k16 + ldmatrix) -------
// A [M,K] fp16, Bt [N,K] fp16.  Tile 128 x BN, BK=64, double-buffered cp.async.
// MODE 0: fp16(x+bias) -> half C;  MODE 1: fp16(gelu(x+bias)) -> half C;
// MODE 2: Cf += x + bias (fp32 residual).
template <int MODE, int BN>
__global__ __launch_bounds__(256, 2) void mma_gemm(
    const __half* __restrict__ A, const __half* __restrict__ Bt,
    const float* __restrict__ bias, void* __restrict__ Cv,
    int M, int N, int K)
{
    constexpr int NT  = BN / 16;       // n8 tiles per warp
    constexpr int NP  = NT / 2;        // ldmatrix n-pairs per warp
    constexpr int ASZ = 128 * 72;      // halves per A stage (stride 72)
    constexpr int BSZ = BN * 72;

    extern __shared__ __half smh[];
    const uint32_t base = smem_u32(smh);
    const uint32_t a_s[2] = { base,            base + (ASZ + BSZ) * 2 };
    const uint32_t b_s[2] = { base + ASZ * 2,  base + (2*ASZ + BSZ) * 2 };

    const int tid  = threadIdx.x;
    const int lane = tid & 31;
    const int warp = tid >> 5;
    const int wm   = (warp & 3) * 32;       // 4 warps over 128 m (2 m16 tiles)
    const int wn   = (warp >> 2) * (BN/2);  // 2 warps over BN
    const int g    = lane >> 2;
    const int tk   = lane & 3;

    const int bm = blockIdx.y * 128;
    const int bn = blockIdx.x * BN;

    // ldmatrix per-lane address offsets (bytes), row stride 144B
    const uint32_t aoff = (uint32_t)(wm + (lane & 15)) * 144u + (uint32_t)(lane >> 4) * 16u;
    const uint32_t boff = (uint32_t)(wn + (lane >> 4) * 8 + (lane & 7)) * 144u
                        + (uint32_t)((lane >> 3) & 1) * 16u;

    float acc[2][NT][4];
    #pragma unroll
    for (int mt = 0; mt < 2; mt++)
        #pragma unroll
        for (int nt = 0; nt < NT; nt++)
            #pragma unroll
            for (int i = 0; i < 4; i++) acc[mt][nt][i] = 0.f;

    auto load_tile = [&](int buf, int k0) {
        #pragma unroll
        for (int i = 0; i < 4; i++) {                   // A: 128 rows x 8 chunks
            int idx = tid + 256 * i;
            int r = idx >> 3, c = idx & 7;
            CP16(a_s[buf] + (uint32_t)(r * 144 + c * 16),
                 A + (size_t)(bm + r) * K + k0 + c * 8);
        }
        #pragma unroll
        for (int i = 0; i < BN / 32; i++) {             // B: BN rows x 8 chunks
            int idx = tid + 256 * i;
            int r = idx >> 3, c = idx & 7;
            CP16(b_s[buf] + (uint32_t)(r * 144 + c * 16),
                 Bt + (size_t)(bn + r) * K + k0 + c * 8);
        }
        CP_COMMIT();
    };

    const int nk = K / 64;
    load_tile(0, 0);

    for (int t = 0; t < nk; t++) {
        const int buf = t & 1;
        if (t + 1 < nk) { load_tile(buf ^ 1, (t + 1) * 64); CP_WAIT(1); }
        else            { CP_WAIT(0); }
        __syncthreads();

        #pragma unroll
        for (int kb = 0; kb < 4; kb++) {
            uint4 af0 = ldmx4(a_s[buf] + aoff + kb * 32);
            uint4 af1 = ldmx4(a_s[buf] + aoff + 2304u + kb * 32);
            const uint32_t a0[4] = { af0.x, af0.y, af0.z, af0.w };
            const uint32_t a1[4] = { af1.x, af1.y, af1.z, af1.w };
            #pragma unroll
            for (int np = 0; np < NP; np++) {
                uint4 bq = ldmx4(b_s[buf] + boff + (uint32_t)np * 2304u + kb * 32);
                mma_f16(acc[0][2*np],   a0, bq.x, bq.y);
                mma_f16(acc[0][2*np+1], a0, bq.z, bq.w);
                mma_f16(acc[1][2*np],   a1, bq.x, bq.y);
                mma_f16(acc[1][2*np+1], a1, bq.z, bq.w);
            }
        }
        __syncthreads();
    }

    #pragma unroll
    for (int mt = 0; mt < 2; mt++) {
        const int row0 = bm + wm + mt * 16 + g;
        #pragma unroll
        for (int nt = 0; nt < NT; nt++) {
            const int col = bn + wn + nt * 8 + 2 * tk;
            float2 bv = *reinterpret_cast<const float2*>(bias + col);
            float o0 = acc[mt][nt][0] + bv.x;
            float o1 = acc[mt][nt][1] + bv.y;
            float o2 = acc[mt][nt][2] + bv.x;
            float o3 = acc[mt][nt][3] + bv.y;
            if (MODE == 0) {
                __half* Ch = (__half*)Cv;
                *reinterpret_cast<__half2*>(Ch + (size_t)row0 * N + col)       = __floats2half2_rn(o0, o1);
                *reinterpret_cast<__half2*>(Ch + (size_t)(row0 + 8) * N + col) = __floats2half2_rn(o2, o3);
            } else if (MODE == 1) {
                __half* Ch = (__half*)Cv;
                *reinterpret_cast<__half2*>(Ch + (size_t)row0 * N + col) =
                    __floats2half2_rn(gelu_tanh(o0), gelu_tanh(o1));
                *reinterpret_cast<__half2*>(Ch + (size_t)(row0 + 8) * N + col) =
                    __floats2half2_rn(gelu_tanh(o2), gelu_tanh(o3));
            } else {
                float* Cf = (float*)Cv;
                float* p0 = Cf + (size_t)row0 * N + col;
                float* p1 = Cf + (size_t)(row0 + 8) * N + col;
                float2 c0 = *reinterpret_cast<const float2*>(p0);
                float2 c1 = *reinterpret_cast<const float2*>(p1);
                *reinterpret_cast<float2*>(p0) = make_float2(o0 + c0.x, o1 + c0.y);
                *reinterpret_cast<float2*>(p1) = make_float2(o2 + c1.x, o3 + c1.y);
            }
        }
    }
}

// ---------------- fp16 tensor-core flash attention ---------------------------
// 128 q-rows per CTA, 8 warps (16 rows each), 64-key tiles, m16n8k16.
#define BQ 128
#define BKV 64
#define ATT_SMEM ((128*72 + 128*72 + 2*2*64*72) * 2)   // 73728 bytes

__global__ __launch_bounds__(256) void flash_attn_tc(
    const __half* __restrict__ qkv, __half* __restrict__ att)
{
    extern __shared__ __half smh[];
    __half* Qs  = smh;                   // [128][72]
    __half* Ps  = Qs + 128 * 72;         // [128][72]
    __half* KV0 = Ps + 128 * 72;         // 2 x (K[64][72], V[64][72])

    const int qb = gridDim.x - 1 - blockIdx.x;   // heavy tiles first
    const int h  = blockIdx.y;
    const int q0 = qb * BQ;
    const int tid = threadIdx.x, lane = tid & 31, w = tid >> 5;
    const int g = lane >> 2, tk = lane & 3;
    const int ld = 3 * EE;
    const int qoff = h * HD;

    // Q tile -> smem (plain copies)
    for (int i = tid; i < 128 * 8; i += 256) {
        int r = i >> 3, c = i & 7;
        *reinterpret_cast<uint4*>(Qs + r * 72 + c * 8) =
            *reinterpret_cast<const uint4*>(qkv + (size_t)(q0 + r) * ld + qoff + c * 8);
    }

    const uint32_t QsB = smem_u32(Qs);
    const uint32_t PsB = smem_u32(Ps);
    const uint32_t KVB = smem_u32(KV0);

    auto loadKV = [&](int buf, int k0) {
        const uint32_t kb_ = KVB + (uint32_t)buf * (2 * 64 * 72 * 2);
        const uint32_t vb_ = kb_ + 64 * 72 * 2;
        #pragma unroll
        for (int i = 0; i < 4; i++) {
            int idx = tid + 256 * i;           // 1024 chunks: 512 K + 512 V
            int sel = idx >> 9;
            int r = (idx >> 3) & 63, c = idx & 7;
            CP16((sel ? vb_ : kb_) + (uint32_t)(r * 144 + c * 16),
                 qkv + (size_t)(k0 + r) * ld + (1 + sel) * EE + qoff + c * 8);
        }
        CP_COMMIT();
    };

    const int kbmax = (q0 + BQ - 1) >> 6;   // inclusive
    loadKV(0, 0);

    float O[8][4];
    float mrow[2] = { -1e30f, -1e30f };
    float lrow[2] = { 0.f, 0.f };
    #pragma unroll
    for (int nt = 0; nt < 8; nt++)
        #pragma unroll
        for (int i = 0; i < 4; i++) O[nt][i] = 0.f;

    // per-lane ldmatrix offsets (bytes)
    const uint32_t qoff_a = (uint32_t)(w * 16 + (lane & 15)) * 144u + (uint32_t)(lane >> 4) * 16u;
    const uint32_t koff_b = (uint32_t)((lane >> 4) * 8 + (lane & 7)) * 144u
                          + (uint32_t)((lane >> 3) & 1) * 16u;
    const uint32_t poff_a = PsB + (uint32_t)(w * 16 + (lane & 15)) * 144u
                          + (uint32_t)(lane >> 4) * 16u;
    __half* Pw = Ps + (w * 16) * 72;

    for (int kb = 0; kb <= kbmax; kb++) {
        const int buf = kb & 1;
        if (kb < kbmax) { loadKV(buf ^ 1, (kb + 1) * BKV); CP_WAIT(1); }
        else            { CP_WAIT(0); }
        __syncthreads();

        const uint32_t KsB = KVB + (uint32_t)buf * (2 * 64 * 72 * 2);
        const uint32_t VsB = KsB + 64 * 72 * 2;
        const int k0 = kb * BKV;

        // ---- S = Q @ K^T ----
        float S[8][4];
        #pragma unroll
        for (int nt = 0; nt < 8; nt++)
            #pragma unroll
            for (int i = 0; i < 4; i++) S[nt][i] = 0.f;

        #pragma unroll
        for (int kk = 0; kk < 4; kk++) {
            uint4 aq = ldmx4(QsB + qoff_a + kk * 32);
            const uint32_t a[4] = { aq.x, aq.y, aq.z, aq.w };
            #pragma unroll
            for (int np = 0; np < 4; np++) {
                uint4 bq = ldmx4(KsB + koff_b + (uint32_t)np * 2304u + kk * 32);
                mma_f16(S[2*np],   a, bq.x, bq.y);
                mma_f16(S[2*np+1], a, bq.z, bq.w);
            }
        }

        // ---- scale + causal mask + online softmax ----
        #pragma unroll
        for (int hf = 0; hf < 2; hf++) {
            const int gq = q0 + w * 16 + g + hf * 8;
            #pragma unroll
            for (int nt = 0; nt < 8; nt++) {
                const int gk = k0 + nt * 8 + 2 * tk;
                float s0 = S[nt][hf*2]   * 0.125f;
                float s1 = S[nt][hf*2+1] * 0.125f;
                S[nt][hf*2]   = (gk     <= gq) ? s0 : -10000.0f;
                S[nt][hf*2+1] = (gk + 1 <= gq) ? s1 : -10000.0f;
            }
            float rm = -1e30f;
            #pragma unroll
            for (int nt = 0; nt < 8; nt++)
                rm = fmaxf(rm, fmaxf(S[nt][hf*2], S[nt][hf*2+1]));
            rm = fmaxf(rm, __shfl_xor_sync(0xffffffffu, rm, 1));
            rm = fmaxf(rm, __shfl_xor_sync(0xffffffffu, rm, 2));
            const float mn = fmaxf(mrow[hf], rm);
            const float corr = __expf(mrow[hf] - mn);
            mrow[hf] = mn;
            float rs = 0.f;
            #pragma unroll
            for (int nt = 0; nt < 8; nt++) {
                float p0 = __expf(S[nt][hf*2]   - mn);
                float p1 = __expf(S[nt][hf*2+1] - mn);
                S[nt][hf*2] = p0; S[nt][hf*2+1] = p1;
                rs += p0 + p1;
            }
            rs += __shfl_xor_sync(0xffffffffu, rs, 1);
            rs += __shfl_xor_sync(0xffffffffu, rs, 2);
            lrow[hf] = lrow[hf] * corr + rs;
            #pragma unroll
            for (int nt = 0; nt < 8; nt++) {
                O[nt][hf*2] *= corr; O[nt][hf*2+1] *= corr;
            }
        }

        // ---- stage P as fp16 (per-warp region) ----
        #pragma unroll
        for (int nt = 0; nt < 8; nt++) {
            *reinterpret_cast<__half2*>(Pw + (g    ) * 72 + nt * 8 + 2 * tk) =
                __floats2half2_rn(S[nt][0], S[nt][1]);
            *reinterpret_cast<__half2*>(Pw + (g + 8) * 72 + nt * 8 + 2 * tk) =
                __floats2half2_rn(S[nt][2], S[nt][3]);
        }
        __syncwarp();

        // ---- O += P @ V ----
        #pragma unroll
        for (int kk = 0; kk < 4; kk++) {
            uint4 ap = ldmx4(poff_a + kk * 32);
            const uint32_t a[4] = { ap.x, ap.y, ap.z, ap.w };
            const uint32_t vrow = VsB + (uint32_t)(kk * 16 + (lane & 15)) * 144u;
            #pragma unroll
            for (int nt = 0; nt < 8; nt++) {
                uint2 bv = ldmx2t(vrow + nt * 16);
                mma_f16(O[nt], a, bv.x, bv.y);
            }
        }
        __syncthreads();   // KV buffer reuse guard
    }

    const float inv0 = 1.0f / lrow[0];
    const float inv1 = 1.0f / lrow[1];
    const int r0 = q0 + w * 16 + g;
    #pragma unroll
    for (int nt = 0; nt < 8; nt++) {
        const int col = qoff + nt * 8 + 2 * tk;
        *reinterpret_cast<__half2*>(att + (size_t)r0 * EE + col) =
            __floats2half2_rn(O[nt][0] * inv0, O[nt][1] * inv0);
        *reinterpret_cast<__half2*>(att + (size_t)(r0 + 8) * EE + col) =
            __floats2half2_rn(O[nt][2] * inv1, O[nt][3] * inv1);
    }
}

// ---------------- host orchestration ---------------------------------------
extern "C" void kernel_launch(void* const* d_in, const int* in_sizes, int n_in,
                              void* d_out, int out_size)
{
    const float* x      = (const float*)d_in[0];
    const float* ln1_w  = (const float*)d_in[1];
    const float* ln1_b  = (const float*)d_in[2];
    const float* attn_w = (const float*)d_in[3];
    const float* attn_b = (const float*)d_in[4];
    const float* proj_w = (const float*)d_in[5];
    const float* proj_b = (const float*)d_in[6];
    const float* ln2_w  = (const float*)d_in[7];
    const float* ln2_b  = (const float*)d_in[8];
    const float* fc_w   = (const float*)d_in[9];
    const float* fc_b   = (const float*)d_in[10];
    const float* fc2_w  = (const float*)d_in[11];
    const float* fc2_b  = (const float*)d_in[12];

    float *h;
    __half *y, *qkv, *att, *m1, *wqkvT, *wprojT, *wfcT, *wfc2T;
    cudaGetSymbolAddress((void**)&h,     g_h);
    cudaGetSymbolAddress((void**)&y,     g_y);
    cudaGetSymbolAddress((void**)&qkv,   g_qkv);
    cudaGetSymbolAddress((void**)&att,   g_att);
    cudaGetSymbolAddress((void**)&m1,    g_m1);
    cudaGetSymbolAddress((void**)&wqkvT, g_wqkvT);
    cudaGetSymbolAddress((void**)&wprojT,g_wprojT);
    cudaGetSymbolAddress((void**)&wfcT,  g_wfcT);
    cudaGetSymbolAddress((void**)&wfc2T, g_wfc2T);

    constexpr int SMEM_128 = 2 * (128 + 128) * 144;   // 73728 B
    constexpr int SMEM_64  = 2 * (128 +  64) * 144;   // 55296 B
    cudaFuncSetAttribute(mma_gemm<0,128>, cudaFuncAttributeMaxDynamicSharedMemorySize, SMEM_128);
    cudaFuncSetAttribute(mma_gemm<1,128>, cudaFuncAttributeMaxDynamicSharedMemorySize, SMEM_128);
    cudaFuncSetAttribute(mma_gemm<2,64>,  cudaFuncAttributeMaxDynamicSharedMemorySize, SMEM_64);
    cudaFuncSetAttribute(flash_attn_tc,   cudaFuncAttributeMaxDynamicSharedMemorySize, ATT_SMEM);

    // transpose all weights to fp16 [N][K] once per replay
    const dim3 tb(32, 8);
    transpose_half_kernel<<<dim3(3*EE/32, EE/32, NL),   tb>>>(attn_w, wqkvT,  EE,   3*EE);
    transpose_half_kernel<<<dim3(EE/32,   EE/32, NL),   tb>>>(proj_w, wprojT, EE,   EE);
    transpose_half_kernel<<<dim3(4*EE/32, EE/32, NL),   tb>>>(fc_w,   wfcT,   EE,   4*EE);
    transpose_half_kernel<<<dim3(EE/32,   4*EE/32, NL), tb>>>(fc2_w,  wfc2T,  4*EE, EE);

    cudaMemcpyAsync(h, x, (size_t)TT * EE * sizeof(float),
                    cudaMemcpyDeviceToDevice, 0);

    const dim3 blk(256);
    const dim3 gLN(TT);
    const dim3 gQKV(3 * EE / 128, TT / 128);   // (24,16)
    const dim3 gPROJ(EE / 64, TT / 128);       // (16,16)
    const dim3 gFC(4 * EE / 128, TT / 128);    // (32,16)
    const dim3 gFC2(EE / 64, TT / 128);        // (16,16)
    const dim3 gATT(TT / BQ, NH);              // (16,16)

    for (int lyr = 0; lyr < NL; lyr++) {
        const __half* aw  = wqkvT  + (size_t)lyr * EE * 3 * EE;
        const float*  ab  = attn_b + (size_t)lyr * 3 * EE;
        const __half* pw  = wprojT + (size_t)lyr * EE * EE;
        const float*  pb  = proj_b + (size_t)lyr * EE;
        const __half* fw  = wfcT   + (size_t)lyr * EE * 4 * EE;
        const float*  fb  = fc_b   + (size_t)lyr * 4 * EE;
        const __half* f2w = wfc2T  + (size_t)lyr * 4 * EE * EE;
        const float*  f2b = fc2_b  + (size_t)lyr * EE;

        // attn block
        ln_kernel<<<gLN, blk>>>(h, ln1_w + (size_t)lyr * EE, ln1_b + (size_t)lyr * EE, y);
        mma_gemm<0,128><<<gQKV, blk, SMEM_128>>>(y, aw, ab, qkv, TT, 3 * EE, EE);
        flash_attn_tc<<<gATT, blk, ATT_SMEM>>>(qkv, att);
        mma_gemm<2,64><<<gPROJ, blk, SMEM_64>>>(att, pw, pb, h, TT, EE, EE);

        // MLP block
        ln_kernel<<<gLN, blk>>>(h, ln2_w + (size_t)lyr * EE, ln2_b + (size_t)lyr * EE, y);
        mma_gemm<1,128><<<gFC, blk, SMEM_128>>>(y, fw, fb, m1, TT, 4 * EE, EE);
        mma_gemm<2,64><<<gFC2, blk, SMEM_64>>>(m1, f2w, f2b, h, TT, EE, 4 * EE);
    }

    cudaMemcpyAsync(d_out, h, (size_t)TT * EE * sizeof(float),
                    cudaMemcpyDeviceToDevice, 0);
}

// round 8
// speedup vs baseline: 3.3206x; 1.0730x over previous
#include <cuda_runtime.h>
#include <cuda_fp16.h>
#include <math.h>
#include <stdint.h>

// GPT-2 stack: L=8, E=1024, H=16, T=2048, B=1, DH=64, fp32 in/out.
#define TT 2048
#define EE 1024
#define NH 16
#define HD 64
#define NL 8

// ---------------- scratch (device globals; no allocation allowed) ----------
__device__ float  g_h  [TT * EE];        // residual stream (fp32)
__device__ __half g_y  [TT * EE];        // LN output (fp16)
__device__ __half g_qkv[TT * 3 * EE];    // QKV (fp16)
__device__ __half g_att[TT * EE];        // attention output (fp16)
__device__ __half g_m1 [TT * 4 * EE];    // MLP hidden (fp16)

// transposed fp16 weights: wT[n][k]
__device__ __half g_wqkvT[NL * 3 * EE * EE];
__device__ __half g_wprojT[NL * EE * EE];
__device__ __half g_wfcT [NL * 4 * EE * EE];
__device__ __half g_wfc2T[NL * EE * 4 * EE];

// ---------------- helpers ----------------------------------------------------
__device__ __forceinline__ uint32_t smem_u32(const void* p) {
    return (uint32_t)__cvta_generic_to_shared(p);
}
__device__ __forceinline__ void mma_f16(float c[4], const uint32_t a[4],
                                        uint32_t b0, uint32_t b1) {
    asm volatile(
        "mma.sync.aligned.m16n8k16.row.col.f32.f16.f16.f32 "
        "{%0,%1,%2,%3}, {%4,%5,%6,%7}, {%8,%9}, {%0,%1,%2,%3};\n"
        : "+f"(c[0]), "+f"(c[1]), "+f"(c[2]), "+f"(c[3])
        : "r"(a[0]), "r"(a[1]), "r"(a[2]), "r"(a[3]), "r"(b0), "r"(b1));
}
__device__ __forceinline__ uint4 ldmx4(uint32_t a) {
    uint4 r;
    asm volatile("ldmatrix.sync.aligned.m8n8.x4.shared.b16 {%0,%1,%2,%3}, [%4];"
        : "=r"(r.x), "=r"(r.y), "=r"(r.z), "=r"(r.w) : "r"(a));
    return r;
}
__device__ __forceinline__ uint2 ldmx2t(uint32_t a) {
    uint2 r;
    asm volatile("ldmatrix.sync.aligned.m8n8.x2.trans.shared.b16 {%0,%1}, [%2];"
        : "=r"(r.x), "=r"(r.y) : "r"(a));
    return r;
}
#define CP16(dst, src) asm volatile("cp.async.cg.shared.global [%0], [%1], 16;\n" :: "r"(dst), "l"(src))
#define CP_COMMIT()    asm volatile("cp.async.commit_group;\n")
#define CP_WAIT(n)     asm volatile("cp.async.wait_group %0;\n" :: "n"(n))

__device__ __forceinline__ float gelu_tanh(float x) {
    const float c0 = 0.7978845608028654f;   // sqrt(2/pi)
    float t = tanhf(c0 * (x + 0.044715f * x * x * x));
    return 0.5f * x * (1.0f + t);
}

// ---------------- transpose weights to fp16 [N][K] ---------------------------
__global__ __launch_bounds__(256) void transpose_half_kernel(
    const float* __restrict__ src, __half* __restrict__ dst, int K, int N)
{
    __shared__ float tile[32][33];
    const float* s = src + (size_t)blockIdx.z * K * N;
    __half* d = dst + (size_t)blockIdx.z * K * N;
    const int k0 = blockIdx.y * 32, n0 = blockIdx.x * 32;
    const int tx = threadIdx.x, ty = threadIdx.y;   // 32 x 8
    #pragma unroll
    for (int i = 0; i < 32; i += 8)
        tile[ty + i][tx] = s[(size_t)(k0 + ty + i) * N + n0 + tx];
    __syncthreads();
    #pragma unroll
    for (int i = 0; i < 32; i += 8)
        d[(size_t)(n0 + ty + i) * K + k0 + tx] = __float2half(tile[tx][ty + i]);
}

// ---------------- LayerNorm: one block per token row ------------------------
__global__ __launch_bounds__(256) void ln_kernel(
    const float* __restrict__ h, const float* __restrict__ w,
    const float* __restrict__ b, __half* __restrict__ y)
{
    const int row = blockIdx.x;
    const int tid = threadIdx.x;
    const float4* hr = reinterpret_cast<const float4*>(h + (size_t)row * EE);
    float4 v = hr[tid];
    float s  = v.x + v.y + v.z + v.w;
    float sq = v.x*v.x + v.y*v.y + v.z*v.z + v.w*v.w;

    __shared__ float ss[8], ssq[8];
    #pragma unroll
    for (int off = 16; off > 0; off >>= 1) {
        s  += __shfl_xor_sync(0xffffffffu, s,  off);
        sq += __shfl_xor_sync(0xffffffffu, sq, off);
    }
    int lane = tid & 31, wid = tid >> 5;
    if (lane == 0) { ss[wid] = s; ssq[wid] = sq; }
    __syncthreads();
    if (tid == 0) {
        float S = 0.f, Q = 0.f;
        #pragma unroll
        for (int i = 0; i < 8; i++) { S += ss[i]; Q += ssq[i]; }
        ss[0] = S; ssq[0] = Q;
    }
    __syncthreads();
    const float mu  = ss[0] * (1.0f / EE);
    const float var = ssq[0] * (1.0f / EE) - mu * mu;
    const float inv = rsqrtf(var + 1e-5f);

    float4 wv = reinterpret_cast<const float4*>(w)[tid];
    float4 bv = reinterpret_cast<const float4*>(b)[tid];
    __half2* yr = reinterpret_cast<__half2*>(y + (size_t)row * EE);
    yr[tid*2]   = __floats2half2_rn((v.x - mu) * inv * wv.x + bv.x,
                                    (v.y - mu) * inv * wv.y + bv.y);
    yr[tid*2+1] = __floats2half2_rn((v.z - mu) * inv * wv.z + bv.z,
                                    (v.w - mu) * inv * wv.w + bv.w);
}

// ---------------- fp16 tensor-core GEMM (m16n8k16 + ldmatrix, 1 sync/tile) ---
// MODE 0: fp16(x+bias); MODE 1: fp16(gelu(x+bias)); MODE 2: Cf += x + bias.
template <int MODE, int BN>
__global__ __launch_bounds__(256, 2) void mma_gemm(
    const __half* __restrict__ A, const __half* __restrict__ Bt,
    const float* __restrict__ bias, void* __restrict__ Cv,
    int M, int N, int K)
{
    constexpr int NT  = BN / 16;
    constexpr int NP  = NT / 2;
    constexpr int ASZ = 128 * 72;
    constexpr int BSZ = BN * 72;

    extern __shared__ __half smh[];
    const uint32_t base = smem_u32(smh);
    const uint32_t a_s[2] = { base,            base + (ASZ + BSZ) * 2 };
    const uint32_t b_s[2] = { base + ASZ * 2,  base + (2*ASZ + BSZ) * 2 };

    const int tid  = threadIdx.x;
    const int lane = tid & 31;
    const int warp = tid >> 5;
    const int wm   = (warp & 3) * 32;
    const int wn   = (warp >> 2) * (BN/2);
    const int g    = lane >> 2;
    const int tk   = lane & 3;

    const int bm = blockIdx.y * 128;
    const int bn = blockIdx.x * BN;

    const uint32_t aoff = (uint32_t)(wm + (lane & 15)) * 144u + (uint32_t)(lane >> 4) * 16u;
    const uint32_t boff = (uint32_t)(wn + (lane >> 4) * 8 + (lane & 7)) * 144u
                        + (uint32_t)((lane >> 3) & 1) * 16u;

    float acc[2][NT][4];
    #pragma unroll
    for (int mt = 0; mt < 2; mt++)
        #pragma unroll
        for (int nt = 0; nt < NT; nt++)
            #pragma unroll
            for (int i = 0; i < 4; i++) acc[mt][nt][i] = 0.f;

    auto load_tile = [&](int buf, int k0) {
        #pragma unroll
        for (int i = 0; i < 4; i++) {
            int idx = tid + 256 * i;
            int r = idx >> 3, c = idx & 7;
            CP16(a_s[buf] + (uint32_t)(r * 144 + c * 16),
                 A + (size_t)(bm + r) * K + k0 + c * 8);
        }
        #pragma unroll
        for (int i = 0; i < BN / 32; i++) {
            int idx = tid + 256 * i;
            int r = idx >> 3, c = idx & 7;
            CP16(b_s[buf] + (uint32_t)(r * 144 + c * 16),
                 Bt + (size_t)(bn + r) * K + k0 + c * 8);
        }
        CP_COMMIT();
    };

    const int nk = K / 64;
    load_tile(0, 0);

    for (int t = 0; t < nk; t++) {
        const int buf = t & 1;
        CP_WAIT(0);            // stage t resident (issuing warp)
        __syncthreads();       // all warps: stage t visible, stage t-1 consumed
        if (t + 1 < nk) load_tile(buf ^ 1, (t + 1) * 64);   // refill freed buffer

        #pragma unroll
        for (int kb = 0; kb < 4; kb++) {
            uint4 af0 = ldmx4(a_s[buf] + aoff + kb * 32);
            uint4 af1 = ldmx4(a_s[buf] + aoff + 2304u + kb * 32);
            const uint32_t a0[4] = { af0.x, af0.y, af0.z, af0.w };
            const uint32_t a1[4] = { af1.x, af1.y, af1.z, af1.w };
            #pragma unroll
            for (int np = 0; np < NP; np++) {
                uint4 bq = ldmx4(b_s[buf] + boff + (uint32_t)np * 2304u + kb * 32);
                mma_f16(acc[0][2*np],   a0, bq.x, bq.y);
                mma_f16(acc[0][2*np+1], a0, bq.z, bq.w);
                mma_f16(acc[1][2*np],   a1, bq.x, bq.y);
                mma_f16(acc[1][2*np+1], a1, bq.z, bq.w);
            }
        }
    }

    #pragma unroll
    for (int mt = 0; mt < 2; mt++) {
        const int row0 = bm + wm + mt * 16 + g;
        #pragma unroll
        for (int nt = 0; nt < NT; nt++) {
            const int col = bn + wn + nt * 8 + 2 * tk;
            float2 bv = *reinterpret_cast<const float2*>(bias + col);
            float o0 = acc[mt][nt][0] + bv.x;
            float o1 = acc[mt][nt][1] + bv.y;
            float o2 = acc[mt][nt][2] + bv.x;
            float o3 = acc[mt][nt][3] + bv.y;
            if (MODE == 0) {
                __half* Ch = (__half*)Cv;
                *reinterpret_cast<__half2*>(Ch + (size_t)row0 * N + col)       = __floats2half2_rn(o0, o1);
                *reinterpret_cast<__half2*>(Ch + (size_t)(row0 + 8) * N + col) = __floats2half2_rn(o2, o3);
            } else if (MODE == 1) {
                __half* Ch = (__half*)Cv;
                *reinterpret_cast<__half2*>(Ch + (size_t)row0 * N + col) =
                    __floats2half2_rn(gelu_tanh(o0), gelu_tanh(o1));
                *reinterpret_cast<__half2*>(Ch + (size_t)(row0 + 8) * N + col) =
                    __floats2half2_rn(gelu_tanh(o2), gelu_tanh(o3));
            } else {
                float* Cf = (float*)Cv;
                float* p0 = Cf + (size_t)row0 * N + col;
                float* p1 = Cf + (size_t)(row0 + 8) * N + col;
                float2 c0 = *reinterpret_cast<const float2*>(p0);
                float2 c1 = *reinterpret_cast<const float2*>(p1);
                *reinterpret_cast<float2*>(p0) = make_float2(o0 + c0.x, o1 + c0.y);
                *reinterpret_cast<float2*>(p1) = make_float2(o2 + c1.x, o3 + c1.y);
            }
        }
    }
}

// ---------------- fp16 tensor-core flash attention (1 sync/KV tile) ----------
#define BQ 128
#define BKV 64
#define ATT_SMEM ((128*72 + 128*72 + 2*2*64*72) * 2)   // 73728 bytes
#define LOG2E 1.4426950408889634f

__global__ __launch_bounds__(256, 2) void flash_attn_tc(
    const __half* __restrict__ qkv, __half* __restrict__ att)
{
    extern __shared__ __half smh[];
    __half* Qs  = smh;                   // [128][72]
    __half* Ps  = Qs + 128 * 72;         // [128][72]
    __half* KV0 = Ps + 128 * 72;         // 2 x (K[64][72], V[64][72])

    const int qb = gridDim.x - 1 - blockIdx.x;   // heavy tiles first
    const int h  = blockIdx.y;
    const int q0 = qb * BQ;
    const int tid = threadIdx.x, lane = tid & 31, w = tid >> 5;
    const int g = lane >> 2, tk = lane & 3;
    const int ld = 3 * EE;
    const int qoff = h * HD;

    for (int i = tid; i < 128 * 8; i += 256) {
        int r = i >> 3, c = i & 7;
        *reinterpret_cast<uint4*>(Qs + r * 72 + c * 8) =
            *reinterpret_cast<const uint4*>(qkv + (size_t)(q0 + r) * ld + qoff + c * 8);
    }

    const uint32_t QsB = smem_u32(Qs);
    const uint32_t PsB = smem_u32(Ps);
    const uint32_t KVB = smem_u32(KV0);

    auto loadKV = [&](int buf, int k0) {
        const uint32_t kb_ = KVB + (uint32_t)buf * (2 * 64 * 72 * 2);
        const uint32_t vb_ = kb_ + 64 * 72 * 2;
        #pragma unroll
        for (int i = 0; i < 4; i++) {
            int idx = tid + 256 * i;
            int sel = idx >> 9;
            int r = (idx >> 3) & 63, c = idx & 7;
            CP16((sel ? vb_ : kb_) + (uint32_t)(r * 144 + c * 16),
                 qkv + (size_t)(k0 + r) * ld + (1 + sel) * EE + qoff + c * 8);
        }
        CP_COMMIT();
    };

    const int kbmax = (q0 + BQ - 1) >> 6;   // inclusive
    loadKV(0, 0);

    float O[8][4];
    float mrow[2] = { -1e30f, -1e30f };     // log2-domain running max
    float lrow[2] = { 0.f, 0.f };
    #pragma unroll
    for (int nt = 0; nt < 8; nt++)
        #pragma unroll
        for (int i = 0; i < 4; i++) O[nt][i] = 0.f;

    const uint32_t qoff_a = (uint32_t)(w * 16 + (lane & 15)) * 144u + (uint32_t)(lane >> 4) * 16u;
    const uint32_t koff_b = (uint32_t)((lane >> 4) * 8 + (lane & 7)) * 144u
                          + (uint32_t)((lane >> 3) & 1) * 16u;
    const uint32_t poff_a = PsB + (uint32_t)(w * 16 + (lane & 15)) * 144u
                          + (uint32_t)(lane >> 4) * 16u;
    __half* Pw = Ps + (w * 16) * 72;
    const float SCL2 = 0.125f * LOG2E;       // fold scale + log2(e)
    const float MASK2 = -10000.0f * LOG2E;

    for (int kb = 0; kb <= kbmax; kb++) {
        const int buf = kb & 1;
        CP_WAIT(0);
        __syncthreads();                                 // stage kb visible, kb-1 consumed
        if (kb < kbmax) loadKV(buf ^ 1, (kb + 1) * BKV); // refill freed buffer

        const uint32_t KsB = KVB + (uint32_t)buf * (2 * 64 * 72 * 2);
        const uint32_t VsB = KsB + 64 * 72 * 2;
        const int k0 = kb * BKV;

        // ---- S = Q @ K^T ----
        float S[8][4];
        #pragma unroll
        for (int nt = 0; nt < 8; nt++)
            #pragma unroll
            for (int i = 0; i < 4; i++) S[nt][i] = 0.f;

        #pragma unroll
        for (int kk = 0; kk < 4; kk++) {
            uint4 aq = ldmx4(QsB + qoff_a + kk * 32);
            const uint32_t a[4] = { aq.x, aq.y, aq.z, aq.w };
            #pragma unroll
            for (int np = 0; np < 4; np++) {
                uint4 bq = ldmx4(KsB + koff_b + (uint32_t)np * 2304u + kk * 32);
                mma_f16(S[2*np],   a, bq.x, bq.y);
                mma_f16(S[2*np+1], a, bq.z, bq.w);
            }
        }

        // ---- scale(log2-domain) + causal mask + online softmax ----
        #pragma unroll
        for (int hf = 0; hf < 2; hf++) {
            const int gq = q0 + w * 16 + g + hf * 8;
            #pragma unroll
            for (int nt = 0; nt < 8; nt++) {
                const int gk = k0 + nt * 8 + 2 * tk;
                float s0 = S[nt][hf*2]   * SCL2;
                float s1 = S[nt][hf*2+1] * SCL2;
                S[nt][hf*2]   = (gk     <= gq) ? s0 : MASK2;
                S[nt][hf*2+1] = (gk + 1 <= gq) ? s1 : MASK2;
            }
            float rm = -1e30f;
            #pragma unroll
            for (int nt = 0; nt < 8; nt++)
                rm = fmaxf(rm, fmaxf(S[nt][hf*2], S[nt][hf*2+1]));
            rm = fmaxf(rm, __shfl_xor_sync(0xffffffffu, rm, 1));
            rm = fmaxf(rm, __shfl_xor_sync(0xffffffffu, rm, 2));
            const float mn = fmaxf(mrow[hf], rm);
            const float corr = exp2f(mrow[hf] - mn);
            mrow[hf] = mn;
            float rs = 0.f;
            #pragma unroll
            for (int nt = 0; nt < 8; nt++) {
                float p0 = exp2f(S[nt][hf*2]   - mn);
                float p1 = exp2f(S[nt][hf*2+1] - mn);
                S[nt][hf*2] = p0; S[nt][hf*2+1] = p1;
                rs += p0 + p1;
            }
            rs += __shfl_xor_sync(0xffffffffu, rs, 1);
            rs += __shfl_xor_sync(0xffffffffu, rs, 2);
            lrow[hf] = lrow[hf] * corr + rs;
            #pragma unroll
            for (int nt = 0; nt < 8; nt++) {
                O[nt][hf*2] *= corr; O[nt][hf*2+1] *= corr;
            }
        }

        // ---- stage P as fp16 (per-warp region) ----
        #pragma unroll
        for (int nt = 0; nt < 8; nt++) {
            *reinterpret_cast<__half2*>(Pw + (g    ) * 72 + nt * 8 + 2 * tk) =
                __floats2half2_rn(S[nt][0], S[nt][1]);
            *reinterpret_cast<__half2*>(Pw + (g + 8) * 72 + nt * 8 + 2 * tk) =
                __floats2half2_rn(S[nt][2], S[nt][3]);
        }
        __syncwarp();

        // ---- O += P @ V ----
        #pragma unroll
        for (int kk = 0; kk < 4; kk++) {
            uint4 ap = ldmx4(poff_a + kk * 32);
            const uint32_t a[4] = { ap.x, ap.y, ap.z, ap.w };
            const uint32_t vrow = VsB + (uint32_t)(kk * 16 + (lane & 15)) * 144u;
            #pragma unroll
            for (int nt = 0; nt < 8; nt++) {
                uint2 bv = ldmx2t(vrow + nt * 16);
                mma_f16(O[nt], a, bv.x, bv.y);
            }
        }
    }

    const float inv0 = 1.0f / lrow[0];
    const float inv1 = 1.0f / lrow[1];
    const int r0 = q0 + w * 16 + g;
    #pragma unroll
    for (int nt = 0; nt < 8; nt++) {
        const int col = qoff + nt * 8 + 2 * tk;
        *reinterpret_cast<__half2*>(att + (size_t)r0 * EE + col) =
            __floats2half2_rn(O[nt][0] * inv0, O[nt][1] * inv0);
        *reinterpret_cast<__half2*>(att + (size_t)(r0 + 8) * EE + col) =
            __floats2half2_rn(O[nt][2] * inv1, O[nt][3] * inv1);
    }
}

// ---------------- host orchestration ---------------------------------------
extern "C" void kernel_launch(void* const* d_in, const int* in_sizes, int n_in,
                              void* d_out, int out_size)
{
    const float* x      = (const float*)d_in[0];
    const float* ln1_w  = (const float*)d_in[1];
    const float* ln1_b  = (const float*)d_in[2];
    const float* attn_w = (const float*)d_in[3];
    const float* attn_b = (const float*)d_in[4];
    const float* proj_w = (const float*)d_in[5];
    const float* proj_b = (const float*)d_in[6];
    const float* ln2_w  = (const float*)d_in[7];
    const float* ln2_b  = (const float*)d_in[8];
    const float* fc_w   = (const float*)d_in[9];
    const float* fc_b   = (const float*)d_in[10];
    const float* fc2_w  = (const float*)d_in[11];
    const float* fc2_b  = (const float*)d_in[12];

    float *h;
    __half *y, *qkv, *att, *m1, *wqkvT, *wprojT, *wfcT, *wfc2T;
    cudaGetSymbolAddress((void**)&h,     g_h);
    cudaGetSymbolAddress((void**)&y,     g_y);
    cudaGetSymbolAddress((void**)&qkv,   g_qkv);
    cudaGetSymbolAddress((void**)&att,   g_att);
    cudaGetSymbolAddress((void**)&m1,    g_m1);
    cudaGetSymbolAddress((void**)&wqkvT, g_wqkvT);
    cudaGetSymbolAddress((void**)&wprojT,g_wprojT);
    cudaGetSymbolAddress((void**)&wfcT,  g_wfcT);
    cudaGetSymbolAddress((void**)&wfc2T, g_wfc2T);

    constexpr int SMEM_128 = 2 * (128 + 128) * 144;   // 73728 B
    constexpr int SMEM_64  = 2 * (128 +  64) * 144;   // 55296 B
    cudaFuncSetAttribute(mma_gemm<0,128>, cudaFuncAttributeMaxDynamicSharedMemorySize, SMEM_128);
    cudaFuncSetAttribute(mma_gemm<1,128>, cudaFuncAttributeMaxDynamicSharedMemorySize, SMEM_128);
    cudaFuncSetAttribute(mma_gemm<2,64>,  cudaFuncAttributeMaxDynamicSharedMemorySize, SMEM_64);
    cudaFuncSetAttribute(flash_attn_tc,   cudaFuncAttributeMaxDynamicSharedMemorySize, ATT_SMEM);

    // transpose all weights to fp16 [N][K] once per replay
    const dim3 tb(32, 8);
    transpose_half_kernel<<<dim3(3*EE/32, EE/32, NL),   tb>>>(attn_w, wqkvT,  EE,   3*EE);
    transpose_half_kernel<<<dim3(EE/32,   EE/32, NL),   tb>>>(proj_w, wprojT, EE,   EE);
    transpose_half_kernel<<<dim3(4*EE/32, EE/32, NL),   tb>>>(fc_w,   wfcT,   EE,   4*EE);
    transpose_half_kernel<<<dim3(EE/32,   4*EE/32, NL), tb>>>(fc2_w,  wfc2T,  4*EE, EE);

    cudaMemcpyAsync(h, x, (size_t)TT * EE * sizeof(float),
                    cudaMemcpyDeviceToDevice, 0);

    const dim3 blk(256);
    const dim3 gLN(TT);
    const dim3 gQKV(3 * EE / 128, TT / 128);   // (24,16)
    const dim3 gPROJ(EE / 64, TT / 128);       // (16,16)
    const dim3 gFC(4 * EE / 128, TT / 128);    // (32,16)
    const dim3 gFC2(EE / 64, TT / 128);        // (16,16)
    const dim3 gATT(TT / BQ, NH);              // (16,16)

    for (int lyr = 0; lyr < NL; lyr++) {
        const __half* aw  = wqkvT  + (size_t)lyr * EE * 3 * EE;
        const float*  ab  = attn_b + (size_t)lyr * 3 * EE;
        const __half* pw  = wprojT + (size_t)lyr * EE * EE;
        const float*  pb  = proj_b + (size_t)lyr * EE;
        const __half* fw  = wfcT   + (size_t)lyr * EE * 4 * EE;
        const float*  fb  = fc_b   + (size_t)lyr * 4 * EE;
        const __half* f2w = wfc2T  + (size_t)lyr * 4 * EE * EE;
        const float*  f2b = fc2_b  + (size_t)lyr * EE;

        // attn block
        ln_kernel<<<gLN, blk>>>(h, ln1_w + (size_t)lyr * EE, ln1_b + (size_t)lyr * EE, y);
        mma_gemm<0,128><<<gQKV, blk, SMEM_128>>>(y, aw, ab, qkv, TT, 3 * EE, EE);
        flash_attn_tc<<<gATT, blk, ATT_SMEM>>>(qkv, att);
        mma_gemm<2,64><<<gPROJ, blk, SMEM_64>>>(att, pw, pb, h, TT, EE, EE);

        // MLP block
        ln_kernel<<<gLN, blk>>>(h, ln2_w + (size_t)lyr * EE, ln2_b + (size_t)lyr * EE, y);
        mma_gemm<1,128><<<gFC, blk, SMEM_128>>>(y, fw, fb, m1, TT, 4 * EE, EE);
        mma_gemm<2,64><<<gFC2, blk, SMEM_64>>>(m1, f2w, f2b, h, TT, EE, 4 * EE);
    }

    cudaMemcpyAsync(d_out, h, (size_t)TT * EE * sizeof(float),
                    cudaMemcpyDeviceToDevice, 0);
}